// round 8
// baseline (speedup 1.0000x reference)
#include <cuda_runtime.h>
#include <cstdint>

// ---------------------------------------------------------------- problem dims
constexpr int Bb   = 2;
constexpr int Tt   = 2048;
constexpr int Dd   = 1024;
constexpr int Hh   = 16;
constexpr int HDim = 64;
constexpr int BT   = Bb * Tt;      // 4096
constexpr int BHn  = Bb * Hh;      // 32
constexpr int CH   = 64;           // chunk length (attention)
constexpr int NCH  = Tt / CH;      // 32

// ---------------------------------------------------------------- scratch
__device__ float g_Q[BHn * Tt * HDim];
__device__ float g_K[BHn * Tt * HDim];
__device__ float g_V[BHn * Tt * HDim];
__device__ float g_Y[BHn * Tt * HDim];
__device__ float g_cs[BHn * NCH * HDim * HDim];
__device__ float g_sp[BHn * NCH * HDim * HDim];
// pre-split bf16 operands (uint16 = bf16 bits)
__device__ uint16_t g_Ahi[BT * Dd];
__device__ uint16_t g_Alo[BT * Dd];
__device__ uint16_t g_Whi[4 * Dd * Dd];
__device__ uint16_t g_Wlo[4 * Dd * Dd];

extern __shared__ char dyn_smem[];

// ---------------------------------------------------------------- helpers
// pack two floats to bf16x2: low half = lo_val, high half = hi_val
__device__ __forceinline__ uint32_t packbf(float lo_val, float hi_val) {
    uint32_t r;
    asm("cvt.rn.bf16x2.f32 %0, %1, %2;" : "=r"(r) : "f"(hi_val), "f"(lo_val));
    return r;
}

__device__ __forceinline__ void split4(float4 v, uint2& hi, uint2& lo) {
    uint32_t h01 = packbf(v.x, v.y);
    uint32_t h23 = packbf(v.z, v.w);
    float lx = v.x - __uint_as_float(h01 << 16);
    float ly = v.y - __uint_as_float(h01 & 0xffff0000u);
    float lz = v.z - __uint_as_float(h23 << 16);
    float lw = v.w - __uint_as_float(h23 & 0xffff0000u);
    hi = make_uint2(h01, h23);
    lo = make_uint2(packbf(lx, ly), packbf(lz, lw));
}

__device__ __forceinline__ void mma_bf16(float* c, const uint32_t* a, const uint32_t* b) {
    asm volatile(
        "mma.sync.aligned.m16n8k16.row.col.f32.bf16.bf16.f32 "
        "{%0,%1,%2,%3}, {%4,%5,%6,%7}, {%8,%9}, {%0,%1,%2,%3};"
        : "+f"(c[0]), "+f"(c[1]), "+f"(c[2]), "+f"(c[3])
        : "r"(a[0]), "r"(a[1]), "r"(a[2]), "r"(a[3]), "r"(b[0]), "r"(b[1]));
}

// ---------------------------------------------------------------- converters
// x (row-major f32 [4096][1024]) -> g_Ahi/g_Alo
__global__ __launch_bounds__(256) void convert_x(const float4* __restrict__ src)
{
    int i = blockIdx.x * 256 + threadIdx.x;     // over BT*Dd/4 = 1M float4
    uint2 hi, lo;
    split4(src[i], hi, lo);
    ((uint2*)g_Ahi)[i] = hi;
    ((uint2*)g_Alo)[i] = lo;
}

// four weight matrices -> g_Whi/g_Wlo[z]
__global__ __launch_bounds__(256) void convert_w(const float4* __restrict__ w0,
                                                 const float4* __restrict__ w1,
                                                 const float4* __restrict__ w2,
                                                 const float4* __restrict__ w3)
{
    int z = blockIdx.y;
    const float4* src = (z == 0) ? w0 : (z == 1) ? w1 : (z == 2) ? w2 : w3;
    int i = blockIdx.x * 256 + threadIdx.x;     // over Dd*Dd/4 = 256K float4
    uint2 hi, lo;
    split4(src[i], hi, lo);
    size_t o = (size_t)z * (Dd * Dd / 4) + i;
    ((uint2*)g_Whi)[o] = hi;
    ((uint2*)g_Wlo)[o] = lo;
}

// g_Y (head-major) -> row-major bf16 hi/lo in g_Ahi/g_Alo (X is dead by now)
__global__ __launch_bounds__(256) void convert_y()
{
    int j = blockIdx.x * 256 + threadIdx.x;     // over BT*Dd/4 float4s of g_Y
    int e = j * 4;
    int hd = e & 63;
    int t  = (e >> 6) & 2047;
    int h  = (e >> 17) & 15;
    int b  = e >> 21;
    float4 v = *(const float4*)(g_Y + e);
    uint2 hi, lo;
    split4(v, hi, lo);
    int dst_e = (b * Tt + t) * Dd + h * HDim + hd;   // row-major (m, k)
    ((uint2*)g_Ahi)[dst_e >> 2] = hi;
    ((uint2*)g_Alo)[dst_e >> 2] = lo;
}

// ---------------------------------------------------------------- bf_gemm cfg
constexpr int TM = 128, TN = 128, KC = 32;   // CTA tile + K chunk
constexpr int NKC = Dd / KC;                 // 32
constexpr int PAD_K = 40;                    // bf16 row stride (conflict-free)
constexpr int TILE_B = 128 * PAD_K * 2;      // 10240 bytes per bf16 tile
constexpr int OFF_AHI = 0;
constexpr int OFF_ALO = TILE_B;
constexpr int OFF_BHI = 2 * TILE_B;
constexpr int OFF_BLO = 3 * TILE_B;
constexpr int GEMM_SMEM = 4 * TILE_B;        // 40960 B (static)

// ---------------------------------------------------------------------------
// GEMM: out[m,n] = sum_k A[m,k]*W[widx][n,k] + bias[n], A = g_Ahi/g_Alo.
// mode 0: widx = blockIdx.z (0/1/2), dst = g_Q/g_K/g_V head-major
// mode 1: widx = 3, dst = outp row-major
// ---------------------------------------------------------------------------
__global__ __launch_bounds__(256) void bf_gemm(int mode,
                                               const float* __restrict__ bq,
                                               const float* __restrict__ bk,
                                               const float* __restrict__ bv,
                                               const float* __restrict__ bo,
                                               float* __restrict__ outp)
{
    __shared__ __align__(16) char smem[GEMM_SMEM];
    const int tid  = threadIdx.x;
    const int wid  = tid >> 5;
    const int lane = tid & 31;
    const int z    = blockIdx.z;
    const int bn = blockIdx.x * TN;
    const int bm = blockIdx.y * TM;
    const int widx = (mode == 0) ? z : 3;
    const float* bias = (mode == 1) ? bo : (z == 0) ? bq : (z == 1) ? bk : bv;

    const uint4* Ah = (const uint4*)g_Ahi;       // 8 bf16 per uint4
    const uint4* Al = (const uint4*)g_Alo;
    const uint4* Wh = (const uint4*)g_Whi + (size_t)widx * (Dd * Dd / 8);
    const uint4* Wl = (const uint4*)g_Wlo + (size_t)widx * (Dd * Dd / 8);

    const int m0w = (wid >> 2) * 64;
    const int n0w = (wid & 3) * 32;
    const int lrow  = lane >> 2;
    const int lcol2 = (lane & 3) * 2;

    float c[4][4][4];
#pragma unroll
    for (int mi = 0; mi < 4; mi++)
#pragma unroll
        for (int ni = 0; ni < 4; ni++)
#pragma unroll
            for (int r = 0; r < 4; r++) c[mi][ni][r] = 0.0f;

    // per-thread tile slots: u = tid + t*256, row = u>>2 (0..127), c16 = u&3
    const int row_ld = tid >> 2;
    const int c16    = tid & 3;
    uint4 pah[2], pal[2], pbh[2], pbl[2];

    // prefetch chunk 0
#pragma unroll
    for (int t = 0; t < 2; t++) {
        int row = row_ld + t * 64;
        size_t ga = ((size_t)(bm + row) * Dd) / 8 + c16;
        size_t gb = ((size_t)(bn + row) * Dd) / 8 + c16;
        pah[t] = Ah[ga]; pal[t] = Al[ga];
        pbh[t] = Wh[gb]; pbl[t] = Wl[gb];
    }

    for (int ck = 0; ck < NKC; ck++) {
        // store prefetched tiles to smem
#pragma unroll
        for (int t = 0; t < 2; t++) {
            int row = row_ld + t * 64;
            int boff = row * PAD_K * 2 + c16 * 16;
            *(uint4*)(smem + OFF_AHI + boff) = pah[t];
            *(uint4*)(smem + OFF_ALO + boff) = pal[t];
            *(uint4*)(smem + OFF_BHI + boff) = pbh[t];
            *(uint4*)(smem + OFF_BLO + boff) = pbl[t];
        }
        __syncthreads();

        // prefetch next chunk (hidden under MMAs)
        if (ck + 1 < NKC) {
            const int k0 = (ck + 1) * KC;
#pragma unroll
            for (int t = 0; t < 2; t++) {
                int row = row_ld + t * 64;
                size_t ga = ((size_t)(bm + row) * Dd + k0) / 8 + c16;
                size_t gb = ((size_t)(bn + row) * Dd + k0) / 8 + c16;
                pah[t] = Ah[ga]; pal[t] = Al[ga];
                pbh[t] = Wh[gb]; pbl[t] = Wl[gb];
            }
        }

        // MMAs over the two k16 steps of this chunk
#pragma unroll
        for (int kk = 0; kk < KC; kk += 16) {
            uint32_t ah[4][4], al[4][4];
#pragma unroll
            for (int mi = 0; mi < 4; mi++) {
                int r0 = m0w + mi * 16 + lrow;
                int o00 = (r0 * PAD_K + kk + lcol2) * 2;
                int o10 = ((r0 + 8) * PAD_K + kk + lcol2) * 2;
                ah[mi][0] = *(const uint32_t*)(smem + OFF_AHI + o00);
                ah[mi][1] = *(const uint32_t*)(smem + OFF_AHI + o10);
                ah[mi][2] = *(const uint32_t*)(smem + OFF_AHI + o00 + 16);
                ah[mi][3] = *(const uint32_t*)(smem + OFF_AHI + o10 + 16);
                al[mi][0] = *(const uint32_t*)(smem + OFF_ALO + o00);
                al[mi][1] = *(const uint32_t*)(smem + OFF_ALO + o10);
                al[mi][2] = *(const uint32_t*)(smem + OFF_ALO + o00 + 16);
                al[mi][3] = *(const uint32_t*)(smem + OFF_ALO + o10 + 16);
            }
            uint32_t bh[4][2], bl[4][2];
#pragma unroll
            for (int ni = 0; ni < 4; ni++) {
                int nr = n0w + ni * 8 + lrow;
                int o = (nr * PAD_K + kk + lcol2) * 2;
                bh[ni][0] = *(const uint32_t*)(smem + OFF_BHI + o);
                bh[ni][1] = *(const uint32_t*)(smem + OFF_BHI + o + 16);
                bl[ni][0] = *(const uint32_t*)(smem + OFF_BLO + o);
                bl[ni][1] = *(const uint32_t*)(smem + OFF_BLO + o + 16);
            }
#pragma unroll
            for (int mi = 0; mi < 4; mi++)
#pragma unroll
                for (int ni = 0; ni < 4; ni++) {
                    mma_bf16(c[mi][ni], ah[mi], bh[ni]);   // Ah*Bh
                    mma_bf16(c[mi][ni], ah[mi], bl[ni]);   // Ah*Bl
                    mma_bf16(c[mi][ni], al[mi], bh[ni]);   // Al*Bh
                }
        }
        __syncthreads();
    }

    // ---- epilogue
#pragma unroll
    for (int mi = 0; mi < 4; mi++) {
        int row0 = bm + m0w + mi * 16 + lrow;
        int row1 = row0 + 8;
#pragma unroll
        for (int ni = 0; ni < 4; ni++) {
            int n = bn + n0w + ni * 8 + lcol2;
            float b0 = bias[n], b1 = bias[n + 1];
            float2 v0 = make_float2(c[mi][ni][0] + b0, c[mi][ni][1] + b1);
            float2 v1 = make_float2(c[mi][ni][2] + b0, c[mi][ni][3] + b1);
            if (mode == 0) {
                float* base = (z == 0) ? g_Q : (z == 1) ? g_K : g_V;
                int h = n >> 6, hd = n & 63;
                int bb0 = row0 >> 11, t0 = row0 & 2047;
                int bb1 = row1 >> 11, t1 = row1 & 2047;
                *(float2*)(base + (((size_t)(bb0 * Hh + h) * Tt) + t0) * HDim + hd) = v0;
                *(float2*)(base + (((size_t)(bb1 * Hh + h) * Tt) + t1) * HDim + hd) = v1;
            } else {
                *(float2*)(outp + (size_t)row0 * Dd + n) = v0;
                *(float2*)(outp + (size_t)row1 * Dd + n) = v1;
            }
        }
    }
}

// ---------------------------------------------------------------------------
// Per-chunk state sums: M[p,n] = sum_{t in chunk} V[t,p] * K[t,n]
// ---------------------------------------------------------------------------
__global__ __launch_bounds__(256) void chunk_sums()
{
    __shared__ float Ks[64 * 64];
    __shared__ float Vs[64 * 64];
    const int bh = blockIdx.y, c = blockIdx.x;
    const int tid = threadIdx.x;
    const float* Kg = g_K + ((size_t)bh * Tt + c * CH) * HDim;
    const float* Vg = g_V + ((size_t)bh * Tt + c * CH) * HDim;
    for (int i = tid; i < 1024; i += 256) {
        ((float4*)Ks)[i] = ((const float4*)Kg)[i];
        ((float4*)Vs)[i] = ((const float4*)Vg)[i];
    }
    __syncthreads();
    const int tx = tid & 15, ty = tid >> 4;
    float acc[4][4];
#pragma unroll
    for (int i = 0; i < 4; i++)
#pragma unroll
        for (int j = 0; j < 4; j++) acc[i][j] = 0.0f;
#pragma unroll 4
    for (int t = 0; t < 64; t++) {
        float rv[4], rk[4];
#pragma unroll
        for (int i = 0; i < 4; i++) rv[i] = Vs[t * 64 + ty * 4 + i];
#pragma unroll
        for (int j = 0; j < 4; j++) rk[j] = Ks[t * 64 + tx * 4 + j];
#pragma unroll
        for (int i = 0; i < 4; i++)
#pragma unroll
            for (int j = 0; j < 4; j++) acc[i][j] += rv[i] * rk[j];
    }
    float* dst = g_cs + ((size_t)bh * NCH + c) * 4096;
#pragma unroll
    for (int i = 0; i < 4; i++)
#pragma unroll
        for (int j = 0; j < 4; j++)
            dst[(ty * 4 + i) * 64 + tx * 4 + j] = acc[i][j];
}

// ---------------------------------------------------------------------------
// Exclusive prefix over chunks
// ---------------------------------------------------------------------------
__global__ __launch_bounds__(256) void prefix_kernel()
{
    const int bh = blockIdx.x;
    for (int e = threadIdx.x; e < 4096; e += 256) {
        float acc = 0.0f;
#pragma unroll
        for (int c = 0; c < NCH; c++) {
            size_t off = ((size_t)bh * NCH + c) * 4096 + e;
            g_sp[off] = acc;
            acc += g_cs[off];
        }
    }
}

// ---------------------------------------------------------------------------
// Intra-chunk attention + inter-chunk state term
// ---------------------------------------------------------------------------
__global__ __launch_bounds__(256) void attn_kernel()
{
    float* Qs = (float*)dyn_smem;      // [64][65]
    float* Ks = Qs + 64 * 65;
    float* Vs = Ks + 64 * 65;
    float* Sp = Vs + 64 * 65;
    float* Am = Sp + 64 * 65;
    const int bh = blockIdx.y, c = blockIdx.x;
    const int tid = threadIdx.x;
    const float* Qg = g_Q + ((size_t)bh * Tt + c * CH) * HDim;
    const float* Kg = g_K + ((size_t)bh * Tt + c * CH) * HDim;
    const float* Vg = g_V + ((size_t)bh * Tt + c * CH) * HDim;
    const float* Sg = g_sp + ((size_t)bh * NCH + c) * 4096;

    for (int i = tid; i < 1024; i += 256) {
        int r = i >> 4;
        int c4 = (i & 15) << 2;
        float4 q = *(const float4*)(Qg + r * 64 + c4);
        float4 k = *(const float4*)(Kg + r * 64 + c4);
        float4 v = *(const float4*)(Vg + r * 64 + c4);
        float4 s = *(const float4*)(Sg + r * 64 + c4);
        Qs[r * 65 + c4 + 0] = q.x; Qs[r * 65 + c4 + 1] = q.y; Qs[r * 65 + c4 + 2] = q.z; Qs[r * 65 + c4 + 3] = q.w;
        Ks[r * 65 + c4 + 0] = k.x; Ks[r * 65 + c4 + 1] = k.y; Ks[r * 65 + c4 + 2] = k.z; Ks[r * 65 + c4 + 3] = k.w;
        Vs[r * 65 + c4 + 0] = v.x; Vs[r * 65 + c4 + 1] = v.y; Vs[r * 65 + c4 + 2] = v.z; Vs[r * 65 + c4 + 3] = v.w;
        Sp[r * 65 + c4 + 0] = s.x; Sp[r * 65 + c4 + 1] = s.y; Sp[r * 65 + c4 + 2] = s.z; Sp[r * 65 + c4 + 3] = s.w;
    }
    __syncthreads();

    const int tx = tid & 15, ty = tid >> 4;

    {
        float a[4][4];
#pragma unroll
        for (int i = 0; i < 4; i++)
#pragma unroll
            for (int j = 0; j < 4; j++) a[i][j] = 0.0f;
#pragma unroll 4
        for (int n = 0; n < 64; n++) {
            float rq[4], rk[4];
#pragma unroll
            for (int i = 0; i < 4; i++) rq[i] = Qs[(ty * 4 + i) * 65 + n];
#pragma unroll
            for (int j = 0; j < 4; j++) rk[j] = Ks[(tx * 4 + j) * 65 + n];
#pragma unroll
            for (int i = 0; i < 4; i++)
#pragma unroll
                for (int j = 0; j < 4; j++) a[i][j] += rq[i] * rk[j];
        }
#pragma unroll
        for (int i = 0; i < 4; i++)
#pragma unroll
            for (int j = 0; j < 4; j++) {
                int t = ty * 4 + i, s = tx * 4 + j;
                Am[t * 65 + s] = (s <= t) ? a[i][j] : 0.0f;
            }
    }
    __syncthreads();

    float y[4][4];
#pragma unroll
    for (int i = 0; i < 4; i++)
#pragma unroll
        for (int j = 0; j < 4; j++) y[i][j] = 0.0f;
#pragma unroll 4
    for (int s = 0; s < 64; s++) {
        float ra[4], rv[4];
#pragma unroll
        for (int i = 0; i < 4; i++) ra[i] = Am[(ty * 4 + i) * 65 + s];
#pragma unroll
        for (int j = 0; j < 4; j++) rv[j] = Vs[s * 65 + tx * 4 + j];
#pragma unroll
        for (int i = 0; i < 4; i++)
#pragma unroll
            for (int j = 0; j < 4; j++) y[i][j] += ra[i] * rv[j];
    }
#pragma unroll 4
    for (int n = 0; n < 64; n++) {
        float rq[4], rs[4];
#pragma unroll
        for (int i = 0; i < 4; i++) rq[i] = Qs[(ty * 4 + i) * 65 + n];
#pragma unroll
        for (int j = 0; j < 4; j++) rs[j] = Sp[(tx * 4 + j) * 65 + n];
#pragma unroll
        for (int i = 0; i < 4; i++)
#pragma unroll
            for (int j = 0; j < 4; j++) y[i][j] += rq[i] * rs[j];
    }

    float* Yg = g_Y + ((size_t)bh * Tt + c * CH) * HDim;
#pragma unroll
    for (int i = 0; i < 4; i++)
#pragma unroll
        for (int j = 0; j < 4; j++)
            Yg[(ty * 4 + i) * 64 + tx * 4 + j] = y[i][j];
}

// ---------------------------------------------------------------------------
extern "C" void kernel_launch(void* const* d_in, const int* in_sizes, int n_in,
                              void* d_out, int out_size)
{
    const float* x  = (const float*)d_in[0];
    const float* Wq = (const float*)d_in[1];
    const float* bq = (const float*)d_in[2];
    const float* Wk = (const float*)d_in[3];
    const float* bk = (const float*)d_in[4];
    const float* Wv = (const float*)d_in[5];
    const float* bv = (const float*)d_in[6];
    const float* Wo = (const float*)d_in[7];
    const float* bo = (const float*)d_in[8];
    float* out = (float*)d_out;

    cudaFuncSetAttribute(attn_kernel, cudaFuncAttributeMaxDynamicSharedMemorySize, 5 * 64 * 65 * 4);

    convert_x<<<BT * Dd / 4 / 256, 256>>>((const float4*)x);
    convert_w<<<dim3(Dd * Dd / 4 / 256, 4), 256>>>((const float4*)Wq, (const float4*)Wk,
                                                   (const float4*)Wv, (const float4*)Wo);
    bf_gemm<<<dim3(Dd / TN, BT / TM, 3), 256>>>(0, bq, bk, bv, bo, nullptr);
    chunk_sums<<<dim3(NCH, BHn), 256>>>();
    prefix_kernel<<<BHn, 256>>>();
    attn_kernel<<<dim3(NCH, BHn), 256, 5 * 64 * 65 * 4>>>();
    convert_y<<<BT * Dd / 4 / 256, 256>>>();
    bf_gemm<<<dim3(Dd / TN, BT / TM, 1), 256>>>(1, bq, bk, bv, bo, out);
}

// round 9
// speedup vs baseline: 1.1856x; 1.1856x over previous
#include <cuda_runtime.h>
#include <cstdint>

// ---------------------------------------------------------------- problem dims
constexpr int Bb   = 2;
constexpr int Tt   = 2048;
constexpr int Dd   = 1024;
constexpr int Hh   = 16;
constexpr int HDim = 64;
constexpr int BT   = Bb * Tt;      // 4096
constexpr int BHn  = Bb * Hh;      // 32
constexpr int CH   = 64;           // chunk length (attention)
constexpr int NCH  = Tt / CH;      // 32

// ---------------------------------------------------------------- scratch
__device__ float g_Q[BHn * Tt * HDim];
__device__ float g_K[BHn * Tt * HDim];
__device__ float g_V[BHn * Tt * HDim];
__device__ float g_Y[BHn * Tt * HDim];
__device__ float g_cs[BHn * NCH * HDim * HDim];
__device__ float g_sp[BHn * NCH * HDim * HDim];

extern __shared__ char dyn_smem[];

// ---------------------------------------------------------------- helpers
// pack two floats to bf16x2: low half = lo_val, high half = hi_val
__device__ __forceinline__ uint32_t packbf(float lo_val, float hi_val) {
    uint32_t r;
    asm("cvt.rn.bf16x2.f32 %0, %1, %2;" : "=r"(r) : "f"(hi_val), "f"(lo_val));
    return r;
}

__device__ __forceinline__ void mma_bf16(float* c, const uint32_t* a, const uint32_t* b) {
    asm volatile(
        "mma.sync.aligned.m16n8k16.row.col.f32.bf16.bf16.f32 "
        "{%0,%1,%2,%3}, {%4,%5,%6,%7}, {%8,%9}, {%0,%1,%2,%3};"
        : "+f"(c[0]), "+f"(c[1]), "+f"(c[2]), "+f"(c[3])
        : "r"(a[0]), "r"(a[1]), "r"(a[2]), "r"(a[3]), "r"(b[0]), "r"(b[1]));
}

__device__ __forceinline__ void ldmx4(uint32_t* r, uint32_t saddr) {
    asm volatile("ldmatrix.sync.aligned.m8n8.x4.shared.b16 {%0,%1,%2,%3}, [%4];"
                 : "=r"(r[0]), "=r"(r[1]), "=r"(r[2]), "=r"(r[3]) : "r"(saddr));
}

// ---------------------------------------------------------------- tc_gemm cfg
constexpr int TM = 128, TN = 128, KC = 32;   // CTA tile + K chunk (floats)
constexpr int NKC = Dd / KC;                 // 32
constexpr int PAD_K = 40;                    // bf16 row stride (conflict-free)
constexpr int TILE_B = 128 * PAD_K * 2;      // 10240 bytes per bf16 tile
constexpr int OFF_AHI = 0;
constexpr int OFF_ALO = TILE_B;
constexpr int OFF_BHI = 2 * TILE_B;
constexpr int OFF_BLO = 3 * TILE_B;
constexpr int GEMM_SMEM = 4 * TILE_B;        // 40960 B (static)

// ---------------------------------------------------------------------------
// Tensor-core GEMM via mma.sync + ldmatrix (bf16 3-term split):
//   out[m,n] = sum_k A[m,k] * W[n,k] + bias[n]
// mode 0: z = blockIdx.z selects Wq/Wk/Wv + bias, dst = g_Q/g_K/g_V head-major
// mode 1: W = Wo (w0), bias = b0, A gathered from g_Y head-major, dst = outp
// ---------------------------------------------------------------------------
__global__ __launch_bounds__(256) void tc_gemm(const float* __restrict__ Xsrc,
                                               const float* __restrict__ w0,
                                               const float* __restrict__ w1,
                                               const float* __restrict__ w2,
                                               const float* __restrict__ b0p,
                                               const float* __restrict__ b1p,
                                               const float* __restrict__ b2p,
                                               float* __restrict__ outp,
                                               int mode)
{
    __shared__ __align__(16) char smem[GEMM_SMEM];
    const int tid  = threadIdx.x;
    const int wid  = tid >> 5;
    const int lane = tid & 31;
    const int z    = blockIdx.z;
    const int bn = blockIdx.x * TN;
    const int bm = blockIdx.y * TM;
    const float* W    = (z == 0) ? w0 : (z == 1) ? w1 : w2;
    const float* bias = (z == 0) ? b0p : (z == 1) ? b1p : b2p;

    uint32_t sbase;
    {
        asm("{ .reg .u64 t; cvta.to.shared.u64 t, %1; cvt.u32.u64 %0, t; }"
            : "=r"(sbase) : "l"((const void*)smem));
    }

    const int m0w = (wid >> 2) * 64;      // warp row offset
    const int n0w = (wid & 3) * 32;       // warp col offset
    const int lrow  = lane >> 2;
    const int lcol2 = (lane & 3) * 2;

    // ldmatrix per-lane base offsets (bytes), before mi/np/kk terms
    const uint32_t a_lane = (uint32_t)(((m0w + ((lane >> 3) & 1) * 8 + (lane & 7)) * PAD_K
                                        + (lane >> 4) * 8) * 2);
    const uint32_t b_lane = (uint32_t)(((n0w + (lane >> 4) * 8 + (lane & 7)) * PAD_K
                                        + ((lane >> 3) & 1) * 8) * 2);

    float c[4][4][4];
#pragma unroll
    for (int mi = 0; mi < 4; mi++)
#pragma unroll
        for (int ni = 0; ni < 4; ni++)
#pragma unroll
            for (int r = 0; r < 4; r++) c[mi][ni][r] = 0.0f;

    float4 pa[4], pb[4];

    // ---- prefetch chunk 0 into registers
#pragma unroll
    for (int t = 0; t < 4; t++) {
        int u = tid + t * 256, row = u >> 3, c4 = (u & 7) * 4;
        if (mode == 0) {
            pa[t] = *(const float4*)(Xsrc + (size_t)(bm + row) * Dd + c4);
        } else {
            int m = bm + row, b = m >> 11, tt = m & 2047;
            int h = c4 >> 6, hd = c4 & 63;
            pa[t] = *(const float4*)(g_Y + (((size_t)(b * Hh + h) * Tt) + tt) * HDim + hd);
        }
        pb[t] = *(const float4*)(W + (size_t)(bn + row) * Dd + c4);
    }

    for (int ck = 0; ck < NKC; ck++) {
        // ---- convert regs -> bf16 hi/lo tiles in smem
#pragma unroll
        for (int t = 0; t < 4; t++) {
            int u = tid + t * 256, row = u >> 3, c4 = (u & 7) * 4;
            int boff = (row * PAD_K + c4) * 2;
            {
                float4 v = pa[t];
                uint32_t h01 = packbf(v.x, v.y);
                uint32_t h23 = packbf(v.z, v.w);
                float lx = v.x - __uint_as_float(h01 << 16);
                float ly = v.y - __uint_as_float(h01 & 0xffff0000u);
                float lz = v.z - __uint_as_float(h23 << 16);
                float lw = v.w - __uint_as_float(h23 & 0xffff0000u);
                *(uint2*)(smem + OFF_AHI + boff) = make_uint2(h01, h23);
                *(uint2*)(smem + OFF_ALO + boff) = make_uint2(packbf(lx, ly), packbf(lz, lw));
            }
            {
                float4 v = pb[t];
                uint32_t h01 = packbf(v.x, v.y);
                uint32_t h23 = packbf(v.z, v.w);
                float lx = v.x - __uint_as_float(h01 << 16);
                float ly = v.y - __uint_as_float(h01 & 0xffff0000u);
                float lz = v.z - __uint_as_float(h23 << 16);
                float lw = v.w - __uint_as_float(h23 & 0xffff0000u);
                *(uint2*)(smem + OFF_BHI + boff) = make_uint2(h01, h23);
                *(uint2*)(smem + OFF_BLO + boff) = make_uint2(packbf(lx, ly), packbf(lz, lw));
            }
        }
        __syncthreads();

        // ---- prefetch next chunk (LDG latency hidden under the MMAs below)
        if (ck + 1 < NKC) {
            const int k0 = (ck + 1) * KC;
#pragma unroll
            for (int t = 0; t < 4; t++) {
                int u = tid + t * 256, row = u >> 3, c4 = (u & 7) * 4;
                if (mode == 0) {
                    pa[t] = *(const float4*)(Xsrc + (size_t)(bm + row) * Dd + k0 + c4);
                } else {
                    int m = bm + row, b = m >> 11, tt = m & 2047;
                    int k = k0 + c4, h = k >> 6, hd = k & 63;
                    pa[t] = *(const float4*)(g_Y + (((size_t)(b * Hh + h) * Tt) + tt) * HDim + hd);
                }
                pb[t] = *(const float4*)(W + (size_t)(bn + row) * Dd + k0 + c4);
            }
        }

        // ---- MMAs over the two k16 steps of this chunk
#pragma unroll
        for (int kk = 0; kk < KC; kk += 16) {
            uint32_t ah[4][4], al[4][4];
#pragma unroll
            for (int mi = 0; mi < 4; mi++) {
                uint32_t ad = sbase + OFF_AHI + a_lane + (uint32_t)((mi * 16 * PAD_K + kk) * 2);
                ldmx4(ah[mi], ad);
                ldmx4(al[mi], ad + (OFF_ALO - OFF_AHI));
            }
            uint32_t bh[4][2], bl[4][2];
#pragma unroll
            for (int np = 0; np < 2; np++) {
                uint32_t bd = sbase + OFF_BHI + b_lane + (uint32_t)((np * 16 * PAD_K + kk) * 2);
                uint32_t r[4];
                ldmx4(r, bd);
                bh[np * 2][0] = r[0]; bh[np * 2][1] = r[1];
                bh[np * 2 + 1][0] = r[2]; bh[np * 2 + 1][1] = r[3];
                ldmx4(r, bd + (OFF_BLO - OFF_BHI));
                bl[np * 2][0] = r[0]; bl[np * 2][1] = r[1];
                bl[np * 2 + 1][0] = r[2]; bl[np * 2 + 1][1] = r[3];
            }
#pragma unroll
            for (int mi = 0; mi < 4; mi++)
#pragma unroll
                for (int ni = 0; ni < 4; ni++) {
                    mma_bf16(c[mi][ni], ah[mi], bh[ni]);   // Ah*Bh
                    mma_bf16(c[mi][ni], ah[mi], bl[ni]);   // Ah*Bl
                    mma_bf16(c[mi][ni], al[mi], bh[ni]);   // Al*Bh
                }
        }
        __syncthreads();
    }

    // ---- epilogue
#pragma unroll
    for (int mi = 0; mi < 4; mi++) {
        int row0 = bm + m0w + mi * 16 + lrow;
        int row1 = row0 + 8;
#pragma unroll
        for (int ni = 0; ni < 4; ni++) {
            int n = bn + n0w + ni * 8 + lcol2;
            float bb0 = bias[n], bb1 = bias[n + 1];
            float2 v0 = make_float2(c[mi][ni][0] + bb0, c[mi][ni][1] + bb1);
            float2 v1 = make_float2(c[mi][ni][2] + bb0, c[mi][ni][3] + bb1);
            if (mode == 0) {
                float* base = (z == 0) ? g_Q : (z == 1) ? g_K : g_V;
                int h = n >> 6, hd = n & 63;
                int batch0 = row0 >> 11, t0 = row0 & 2047;
                int batch1 = row1 >> 11, t1 = row1 & 2047;
                *(float2*)(base + (((size_t)(batch0 * Hh + h) * Tt) + t0) * HDim + hd) = v0;
                *(float2*)(base + (((size_t)(batch1 * Hh + h) * Tt) + t1) * HDim + hd) = v1;
            } else {
                *(float2*)(outp + (size_t)row0 * Dd + n) = v0;
                *(float2*)(outp + (size_t)row1 * Dd + n) = v1;
            }
        }
    }
}

// ---------------------------------------------------------------------------
// Per-chunk state sums: M[p,n] = sum_{t in chunk} V[t,p] * K[t,n]
// ---------------------------------------------------------------------------
__global__ __launch_bounds__(256) void chunk_sums()
{
    __shared__ float Ks[64 * 64];
    __shared__ float Vs[64 * 64];
    const int bh = blockIdx.y, c = blockIdx.x;
    const int tid = threadIdx.x;
    const float* Kg = g_K + ((size_t)bh * Tt + c * CH) * HDim;
    const float* Vg = g_V + ((size_t)bh * Tt + c * CH) * HDim;
    for (int i = tid; i < 1024; i += 256) {
        ((float4*)Ks)[i] = ((const float4*)Kg)[i];
        ((float4*)Vs)[i] = ((const float4*)Vg)[i];
    }
    __syncthreads();
    const int tx = tid & 15, ty = tid >> 4;
    float acc[4][4];
#pragma unroll
    for (int i = 0; i < 4; i++)
#pragma unroll
        for (int j = 0; j < 4; j++) acc[i][j] = 0.0f;
#pragma unroll 4
    for (int t = 0; t < 64; t++) {
        float rv[4], rk[4];
#pragma unroll
        for (int i = 0; i < 4; i++) rv[i] = Vs[t * 64 + ty * 4 + i];
#pragma unroll
        for (int j = 0; j < 4; j++) rk[j] = Ks[t * 64 + tx * 4 + j];
#pragma unroll
        for (int i = 0; i < 4; i++)
#pragma unroll
            for (int j = 0; j < 4; j++) acc[i][j] += rv[i] * rk[j];
    }
    float* dst = g_cs + ((size_t)bh * NCH + c) * 4096;
#pragma unroll
    for (int i = 0; i < 4; i++)
#pragma unroll
        for (int j = 0; j < 4; j++)
            dst[(ty * 4 + i) * 64 + tx * 4 + j] = acc[i][j];
}

// ---------------------------------------------------------------------------
// Exclusive prefix over chunks
// ---------------------------------------------------------------------------
__global__ __launch_bounds__(256) void prefix_kernel()
{
    const int bh = blockIdx.x;
    for (int e = threadIdx.x; e < 4096; e += 256) {
        float acc = 0.0f;
#pragma unroll
        for (int c = 0; c < NCH; c++) {
            size_t off = ((size_t)bh * NCH + c) * 4096 + e;
            g_sp[off] = acc;
            acc += g_cs[off];
        }
    }
}

// ---------------------------------------------------------------------------
// Intra-chunk attention + inter-chunk state term
// ---------------------------------------------------------------------------
__global__ __launch_bounds__(256) void attn_kernel()
{
    float* Qs = (float*)dyn_smem;      // [64][65]
    float* Ks = Qs + 64 * 65;
    float* Vs = Ks + 64 * 65;
    float* Sp = Vs + 64 * 65;
    float* Am = Sp + 64 * 65;
    const int bh = blockIdx.y, c = blockIdx.x;
    const int tid = threadIdx.x;
    const float* Qg = g_Q + ((size_t)bh * Tt + c * CH) * HDim;
    const float* Kg = g_K + ((size_t)bh * Tt + c * CH) * HDim;
    const float* Vg = g_V + ((size_t)bh * Tt + c * CH) * HDim;
    const float* Sg = g_sp + ((size_t)bh * NCH + c) * 4096;

    for (int i = tid; i < 1024; i += 256) {
        int r = i >> 4;
        int c4 = (i & 15) << 2;
        float4 q = *(const float4*)(Qg + r * 64 + c4);
        float4 k = *(const float4*)(Kg + r * 64 + c4);
        float4 v = *(const float4*)(Vg + r * 64 + c4);
        float4 s = *(const float4*)(Sg + r * 64 + c4);
        Qs[r * 65 + c4 + 0] = q.x; Qs[r * 65 + c4 + 1] = q.y; Qs[r * 65 + c4 + 2] = q.z; Qs[r * 65 + c4 + 3] = q.w;
        Ks[r * 65 + c4 + 0] = k.x; Ks[r * 65 + c4 + 1] = k.y; Ks[r * 65 + c4 + 2] = k.z; Ks[r * 65 + c4 + 3] = k.w;
        Vs[r * 65 + c4 + 0] = v.x; Vs[r * 65 + c4 + 1] = v.y; Vs[r * 65 + c4 + 2] = v.z; Vs[r * 65 + c4 + 3] = v.w;
        Sp[r * 65 + c4 + 0] = s.x; Sp[r * 65 + c4 + 1] = s.y; Sp[r * 65 + c4 + 2] = s.z; Sp[r * 65 + c4 + 3] = s.w;
    }
    __syncthreads();

    const int tx = tid & 15, ty = tid >> 4;

    {
        float a[4][4];
#pragma unroll
        for (int i = 0; i < 4; i++)
#pragma unroll
            for (int j = 0; j < 4; j++) a[i][j] = 0.0f;
#pragma unroll 4
        for (int n = 0; n < 64; n++) {
            float rq[4], rk[4];
#pragma unroll
            for (int i = 0; i < 4; i++) rq[i] = Qs[(ty * 4 + i) * 65 + n];
#pragma unroll
            for (int j = 0; j < 4; j++) rk[j] = Ks[(tx * 4 + j) * 65 + n];
#pragma unroll
            for (int i = 0; i < 4; i++)
#pragma unroll
                for (int j = 0; j < 4; j++) a[i][j] += rq[i] * rk[j];
        }
#pragma unroll
        for (int i = 0; i < 4; i++)
#pragma unroll
            for (int j = 0; j < 4; j++) {
                int t = ty * 4 + i, s = tx * 4 + j;
                Am[t * 65 + s] = (s <= t) ? a[i][j] : 0.0f;
            }
    }
    __syncthreads();

    float y[4][4];
#pragma unroll
    for (int i = 0; i < 4; i++)
#pragma unroll
        for (int j = 0; j < 4; j++) y[i][j] = 0.0f;
#pragma unroll 4
    for (int s = 0; s < 64; s++) {
        float ra[4], rv[4];
#pragma unroll
        for (int i = 0; i < 4; i++) ra[i] = Am[(ty * 4 + i) * 65 + s];
#pragma unroll
        for (int j = 0; j < 4; j++) rv[j] = Vs[s * 65 + tx * 4 + j];
#pragma unroll
        for (int i = 0; i < 4; i++)
#pragma unroll
            for (int j = 0; j < 4; j++) y[i][j] += ra[i] * rv[j];
    }
#pragma unroll 4
    for (int n = 0; n < 64; n++) {
        float rq[4], rs[4];
#pragma unroll
        for (int i = 0; i < 4; i++) rq[i] = Qs[(ty * 4 + i) * 65 + n];
#pragma unroll
        for (int j = 0; j < 4; j++) rs[j] = Sp[(tx * 4 + j) * 65 + n];
#pragma unroll
        for (int i = 0; i < 4; i++)
#pragma unroll
            for (int j = 0; j < 4; j++) y[i][j] += rq[i] * rs[j];
    }

    float* Yg = g_Y + ((size_t)bh * Tt + c * CH) * HDim;
#pragma unroll
    for (int i = 0; i < 4; i++)
#pragma unroll
        for (int j = 0; j < 4; j++)
            Yg[(ty * 4 + i) * 64 + tx * 4 + j] = y[i][j];
}

// ---------------------------------------------------------------------------
extern "C" void kernel_launch(void* const* d_in, const int* in_sizes, int n_in,
                              void* d_out, int out_size)
{
    const float* x  = (const float*)d_in[0];
    const float* Wq = (const float*)d_in[1];
    const float* bq = (const float*)d_in[2];
    const float* Wk = (const float*)d_in[3];
    const float* bk = (const float*)d_in[4];
    const float* Wv = (const float*)d_in[5];
    const float* bv = (const float*)d_in[6];
    const float* Wo = (const float*)d_in[7];
    const float* bo = (const float*)d_in[8];
    float* out = (float*)d_out;

    cudaFuncSetAttribute(attn_kernel, cudaFuncAttributeMaxDynamicSharedMemorySize, 5 * 64 * 65 * 4);

    // fused Q/K/V projections (z selects weight/bias/dst)
    tc_gemm<<<dim3(Dd / TN, BT / TM, 3), 256>>>(x, Wq, Wk, Wv, bq, bk, bv, nullptr, 0);
    chunk_sums<<<dim3(NCH, BHn), 256>>>();
    prefix_kernel<<<BHn, 256>>>();
    attn_kernel<<<dim3(NCH, BHn), 256, 5 * 64 * 65 * 4>>>();
    tc_gemm<<<dim3(Dd / TN, BT / TM, 1), 256>>>(nullptr, Wo, nullptr, nullptr, bo, nullptr, nullptr, out, 1);
}

// round 10
// speedup vs baseline: 1.4960x; 1.2618x over previous
#include <cuda_runtime.h>
#include <cstdint>

// ---------------------------------------------------------------- problem dims
constexpr int Bb   = 2;
constexpr int Tt   = 2048;
constexpr int Dd   = 1024;
constexpr int Hh   = 16;
constexpr int HDim = 64;
constexpr int BT   = Bb * Tt;      // 4096
constexpr int BHn  = Bb * Hh;      // 32
constexpr int CH   = 64;           // chunk length (attention)
constexpr int NCH  = Tt / CH;      // 32

// ---------------------------------------------------------------- scratch
__device__ float g_Q[BHn * Tt * HDim];
__device__ float g_K[BHn * Tt * HDim];
__device__ float g_V[BHn * Tt * HDim];
__device__ float g_Y[BHn * Tt * HDim];
__device__ float g_cs[BHn * NCH * HDim * HDim];
__device__ float g_sp[BHn * NCH * HDim * HDim];

extern __shared__ char dyn_smem[];

// ---------------------------------------------------------------- helpers
// pack two floats to bf16x2: low half = lo_val, high half = hi_val
__device__ __forceinline__ uint32_t packbf(float lo_val, float hi_val) {
    uint32_t r;
    asm("cvt.rn.bf16x2.f32 %0, %1, %2;" : "=r"(r) : "f"(hi_val), "f"(lo_val));
    return r;
}

__device__ __forceinline__ void mma_bf16(float* c, const uint32_t* a, const uint32_t* b) {
    asm volatile(
        "mma.sync.aligned.m16n8k16.row.col.f32.bf16.bf16.f32 "
        "{%0,%1,%2,%3}, {%4,%5,%6,%7}, {%8,%9}, {%0,%1,%2,%3};"
        : "+f"(c[0]), "+f"(c[1]), "+f"(c[2]), "+f"(c[3])
        : "r"(a[0]), "r"(a[1]), "r"(a[2]), "r"(a[3]), "r"(b[0]), "r"(b[1]));
}

__device__ __forceinline__ void ldmx4(uint32_t* r, uint32_t saddr) {
    asm volatile("ldmatrix.sync.aligned.m8n8.x4.shared.b16 {%0,%1,%2,%3}, [%4];"
                 : "=r"(r[0]), "=r"(r[1]), "=r"(r[2]), "=r"(r[3]) : "r"(saddr));
}

// ---------------------------------------------------------------- tc_gemm cfg
constexpr int TM = 128, TN = 128, KC = 32;   // CTA tile + K chunk (floats)
constexpr int NKC = Dd / KC;                 // 32
constexpr int PAD_K = 40;                    // bf16 row stride (conflict-free)
constexpr int TILE_B = 128 * PAD_K * 2;      // 10240 bytes per bf16 tile
constexpr int OFF_AHI = 0;
constexpr int OFF_ALO = TILE_B;
constexpr int OFF_BHI = 2 * TILE_B;
constexpr int OFF_BLO = 3 * TILE_B;
constexpr int BUF_B   = 4 * TILE_B;          // 40960 per stage
constexpr int GEMM_SMEM = 2 * BUF_B;         // 81920 (dynamic, double buffer)

// ---------------------------------------------------------------------------
// Tensor-core GEMM via mma.sync + ldmatrix (bf16 3-term split), double-buffered:
//   out[m,n] = sum_k A[m,k] * W[n,k] + bias[n]
// mode 0: z = blockIdx.z selects Wq/Wk/Wv + bias, dst = g_Q/g_K/g_V head-major
// mode 1: W = Wo (w0), bias = b0, A gathered from g_Y head-major, dst = outp
// ---------------------------------------------------------------------------
__global__ __launch_bounds__(256) void tc_gemm(const float* __restrict__ Xsrc,
                                               const float* __restrict__ w0,
                                               const float* __restrict__ w1,
                                               const float* __restrict__ w2,
                                               const float* __restrict__ b0p,
                                               const float* __restrict__ b1p,
                                               const float* __restrict__ b2p,
                                               float* __restrict__ outp,
                                               int mode)
{
    char* smem = dyn_smem;
    const int tid  = threadIdx.x;
    const int wid  = tid >> 5;
    const int lane = tid & 31;
    const int z    = blockIdx.z;
    const int bn = blockIdx.x * TN;
    const int bm = blockIdx.y * TM;
    const float* W    = (z == 0) ? w0 : (z == 1) ? w1 : w2;
    const float* bias = (z == 0) ? b0p : (z == 1) ? b1p : b2p;

    uint32_t sbase;
    asm("{ .reg .u64 t; cvta.to.shared.u64 t, %1; cvt.u32.u64 %0, t; }"
        : "=r"(sbase) : "l"((const void*)smem));

    const int m0w = (wid >> 2) * 64;      // warp row offset
    const int n0w = (wid & 3) * 32;       // warp col offset
    const int lrow  = lane >> 2;
    const int lcol2 = (lane & 3) * 2;

    // ldmatrix per-lane base offsets (bytes)
    const uint32_t a_lane = (uint32_t)(((m0w + ((lane >> 3) & 1) * 8 + (lane & 7)) * PAD_K
                                        + (lane >> 4) * 8) * 2);
    const uint32_t b_lane = (uint32_t)(((n0w + (lane >> 4) * 8 + (lane & 7)) * PAD_K
                                        + ((lane >> 3) & 1) * 8) * 2);

    float c[4][4][4];
#pragma unroll
    for (int mi = 0; mi < 4; mi++)
#pragma unroll
        for (int ni = 0; ni < 4; ni++)
#pragma unroll
            for (int r = 0; r < 4; r++) c[mi][ni][r] = 0.0f;

    float4 pa[4], pb[4];

    // loader: fetch chunk k0 into pa/pb
    auto fetch = [&](int k0) {
#pragma unroll
        for (int t = 0; t < 4; t++) {
            int u = tid + t * 256, row = u >> 3, c4 = (u & 7) * 4;
            if (mode == 0) {
                pa[t] = *(const float4*)(Xsrc + (size_t)(bm + row) * Dd + k0 + c4);
            } else {
                int m = bm + row, b = m >> 11, tt = m & 2047;
                int k = k0 + c4, h = k >> 6, hd = k & 63;
                pa[t] = *(const float4*)(g_Y + (((size_t)(b * Hh + h) * Tt) + tt) * HDim + hd);
            }
            pb[t] = *(const float4*)(W + (size_t)(bn + row) * Dd + k0 + c4);
        }
    };
    // converter: split pa/pb into bf16 hi/lo tiles of buffer `bo`
    auto stash = [&](int bo) {
#pragma unroll
        for (int t = 0; t < 4; t++) {
            int u = tid + t * 256, row = u >> 3, c4 = (u & 7) * 4;
            int boff = bo + (row * PAD_K + c4) * 2;
            {
                float4 v = pa[t];
                uint32_t h01 = packbf(v.x, v.y);
                uint32_t h23 = packbf(v.z, v.w);
                float lx = v.x - __uint_as_float(h01 << 16);
                float ly = v.y - __uint_as_float(h01 & 0xffff0000u);
                float lz = v.z - __uint_as_float(h23 << 16);
                float lw = v.w - __uint_as_float(h23 & 0xffff0000u);
                *(uint2*)(smem + OFF_AHI + boff) = make_uint2(h01, h23);
                *(uint2*)(smem + OFF_ALO + boff) = make_uint2(packbf(lx, ly), packbf(lz, lw));
            }
            {
                float4 v = pb[t];
                uint32_t h01 = packbf(v.x, v.y);
                uint32_t h23 = packbf(v.z, v.w);
                float lx = v.x - __uint_as_float(h01 << 16);
                float ly = v.y - __uint_as_float(h01 & 0xffff0000u);
                float lz = v.z - __uint_as_float(h23 << 16);
                float lw = v.w - __uint_as_float(h23 & 0xffff0000u);
                *(uint2*)(smem + OFF_BHI + boff) = make_uint2(h01, h23);
                *(uint2*)(smem + OFF_BLO + boff) = make_uint2(packbf(lx, ly), packbf(lz, lw));
            }
        }
    };

    // prologue: chunk 0 -> buf 0; prefetch chunk 1
    fetch(0);
    stash(0);
    fetch(KC);

    for (int ck = 0; ck < NKC; ck++) {
        __syncthreads();
        const uint32_t bo = (uint32_t)((ck & 1) * BUF_B);

        // ---- MMA phase on current buffer (issued first, runs async)
#pragma unroll
        for (int kk = 0; kk < KC; kk += 16) {
            uint32_t ah[4][4], al[4][4];
#pragma unroll
            for (int mi = 0; mi < 4; mi++) {
                uint32_t ad = sbase + bo + OFF_AHI + a_lane + (uint32_t)((mi * 16 * PAD_K + kk) * 2);
                ldmx4(ah[mi], ad);
                ldmx4(al[mi], ad + (OFF_ALO - OFF_AHI));
            }
            uint32_t bh[4][2], bl[4][2];
#pragma unroll
            for (int np = 0; np < 2; np++) {
                uint32_t bd = sbase + bo + OFF_BHI + b_lane + (uint32_t)((np * 16 * PAD_K + kk) * 2);
                uint32_t r[4];
                ldmx4(r, bd);
                bh[np * 2][0] = r[0]; bh[np * 2][1] = r[1];
                bh[np * 2 + 1][0] = r[2]; bh[np * 2 + 1][1] = r[3];
                ldmx4(r, bd + (OFF_BLO - OFF_BHI));
                bl[np * 2][0] = r[0]; bl[np * 2][1] = r[1];
                bl[np * 2 + 1][0] = r[2]; bl[np * 2 + 1][1] = r[3];
            }
#pragma unroll
            for (int mi = 0; mi < 4; mi++)
#pragma unroll
                for (int ni = 0; ni < 4; ni++) {
                    mma_bf16(c[mi][ni], ah[mi], bh[ni]);   // Ah*Bh
                    mma_bf16(c[mi][ni], ah[mi], bl[ni]);   // Ah*Bl
                    mma_bf16(c[mi][ni], al[mi], bh[ni]);   // Al*Bh
                }
        }

        // ---- store chunk ck+1 into alternate buffer (under the MMAs)
        if (ck + 1 < NKC) stash(((ck + 1) & 1) * BUF_B);
        // ---- prefetch chunk ck+2 (covered by next iteration's MMA phase)
        if (ck + 2 < NKC) fetch((ck + 2) * KC);
    }

    // ---- epilogue
#pragma unroll
    for (int mi = 0; mi < 4; mi++) {
        int row0 = bm + m0w + mi * 16 + lrow;
        int row1 = row0 + 8;
#pragma unroll
        for (int ni = 0; ni < 4; ni++) {
            int n = bn + n0w + ni * 8 + lcol2;
            float bb0 = bias[n], bb1 = bias[n + 1];
            float2 v0 = make_float2(c[mi][ni][0] + bb0, c[mi][ni][1] + bb1);
            float2 v1 = make_float2(c[mi][ni][2] + bb0, c[mi][ni][3] + bb1);
            if (mode == 0) {
                float* base = (z == 0) ? g_Q : (z == 1) ? g_K : g_V;
                int h = n >> 6, hd = n & 63;
                int batch0 = row0 >> 11, t0 = row0 & 2047;
                int batch1 = row1 >> 11, t1 = row1 & 2047;
                *(float2*)(base + (((size_t)(batch0 * Hh + h) * Tt) + t0) * HDim + hd) = v0;
                *(float2*)(base + (((size_t)(batch1 * Hh + h) * Tt) + t1) * HDim + hd) = v1;
            } else {
                *(float2*)(outp + (size_t)row0 * Dd + n) = v0;
                *(float2*)(outp + (size_t)row1 * Dd + n) = v1;
            }
        }
    }
}

// ---------------------------------------------------------------------------
// Per-chunk state sums: M[p,n] = sum_{t in chunk} V[t,p] * K[t,n]
// 64 threads, 8x8 microtile: 2x FLOP per LDS byte vs 4x4.
// ---------------------------------------------------------------------------
__global__ __launch_bounds__(64) void chunk_sums()
{
    __shared__ float Ks[64 * 64];
    __shared__ float Vs[64 * 64];
    const int bh = blockIdx.y, c = blockIdx.x;
    const int tid = threadIdx.x;
    const float* Kg = g_K + ((size_t)bh * Tt + c * CH) * HDim;
    const float* Vg = g_V + ((size_t)bh * Tt + c * CH) * HDim;
    for (int i = tid; i < 1024; i += 64) {
        ((float4*)Ks)[i] = ((const float4*)Kg)[i];
        ((float4*)Vs)[i] = ((const float4*)Vg)[i];
    }
    __syncthreads();
    const int tx = tid & 7, ty = tid >> 3;
    float acc[8][8];
#pragma unroll
    for (int i = 0; i < 8; i++)
#pragma unroll
        for (int j = 0; j < 8; j++) acc[i][j] = 0.0f;
#pragma unroll 4
    for (int t = 0; t < 64; t++) {
        float rv[8], rk[8];
        *(float4*)(rv)     = *(const float4*)(Vs + t * 64 + ty * 8);
        *(float4*)(rv + 4) = *(const float4*)(Vs + t * 64 + ty * 8 + 4);
        *(float4*)(rk)     = *(const float4*)(Ks + t * 64 + tx * 8);
        *(float4*)(rk + 4) = *(const float4*)(Ks + t * 64 + tx * 8 + 4);
#pragma unroll
        for (int i = 0; i < 8; i++)
#pragma unroll
            for (int j = 0; j < 8; j++) acc[i][j] += rv[i] * rk[j];
    }
    float* dst = g_cs + ((size_t)bh * NCH + c) * 4096;
#pragma unroll
    for (int i = 0; i < 8; i++)
#pragma unroll
        for (int j = 0; j < 8; j += 4)
            *(float4*)(dst + (ty * 8 + i) * 64 + tx * 8 + j) =
                make_float4(acc[i][j], acc[i][j + 1], acc[i][j + 2], acc[i][j + 3]);
}

// ---------------------------------------------------------------------------
// Exclusive prefix over chunks (parallelized: 512 blocks)
// ---------------------------------------------------------------------------
__global__ __launch_bounds__(256) void prefix_kernel()
{
    const int bh = blockIdx.x;
    const int e = blockIdx.y * 256 + threadIdx.x;
    float acc = 0.0f;
#pragma unroll
    for (int c = 0; c < NCH; c++) {
        size_t off = ((size_t)bh * NCH + c) * 4096 + e;
        g_sp[off] = acc;
        acc += g_cs[off];
    }
}

// ---------------------------------------------------------------------------
// Intra-chunk attention + inter-chunk state term.
// 4 smem tiles (Am aliases Ks after phase 1) -> 66560 B -> 3 CTAs/SM.
// ---------------------------------------------------------------------------
__global__ __launch_bounds__(256) void attn_kernel()
{
    float* Qs = (float*)dyn_smem;      // [64][65]
    float* Ks = Qs + 64 * 65;
    float* Vs = Ks + 64 * 65;
    float* Sp = Vs + 64 * 65;
    float* Am = Ks;                    // phase-2 scores overwrite Ks
    const int bh = blockIdx.y, c = blockIdx.x;
    const int tid = threadIdx.x;
    const float* Qg = g_Q + ((size_t)bh * Tt + c * CH) * HDim;
    const float* Kg = g_K + ((size_t)bh * Tt + c * CH) * HDim;
    const float* Vg = g_V + ((size_t)bh * Tt + c * CH) * HDim;
    const float* Sg = g_sp + ((size_t)bh * NCH + c) * 4096;

    for (int i = tid; i < 1024; i += 256) {
        int r = i >> 4;
        int c4 = (i & 15) << 2;
        float4 q = *(const float4*)(Qg + r * 64 + c4);
        float4 k = *(const float4*)(Kg + r * 64 + c4);
        float4 v = *(const float4*)(Vg + r * 64 + c4);
        float4 s = *(const float4*)(Sg + r * 64 + c4);
        Qs[r * 65 + c4 + 0] = q.x; Qs[r * 65 + c4 + 1] = q.y; Qs[r * 65 + c4 + 2] = q.z; Qs[r * 65 + c4 + 3] = q.w;
        Ks[r * 65 + c4 + 0] = k.x; Ks[r * 65 + c4 + 1] = k.y; Ks[r * 65 + c4 + 2] = k.z; Ks[r * 65 + c4 + 3] = k.w;
        Vs[r * 65 + c4 + 0] = v.x; Vs[r * 65 + c4 + 1] = v.y; Vs[r * 65 + c4 + 2] = v.z; Vs[r * 65 + c4 + 3] = v.w;
        Sp[r * 65 + c4 + 0] = s.x; Sp[r * 65 + c4 + 1] = s.y; Sp[r * 65 + c4 + 2] = s.z; Sp[r * 65 + c4 + 3] = s.w;
    }
    __syncthreads();

    const int tx = tid & 15, ty = tid >> 4;

    // Phase 1: a[t][s] = (s<=t) ? dot(Q[t],K[s]) : 0   (held in regs)
    float a[4][4];
    {
#pragma unroll
        for (int i = 0; i < 4; i++)
#pragma unroll
            for (int j = 0; j < 4; j++) a[i][j] = 0.0f;
#pragma unroll 4
        for (int n = 0; n < 64; n++) {
            float rq[4], rk[4];
#pragma unroll
            for (int i = 0; i < 4; i++) rq[i] = Qs[(ty * 4 + i) * 65 + n];
#pragma unroll
            for (int j = 0; j < 4; j++) rk[j] = Ks[(tx * 4 + j) * 65 + n];
#pragma unroll
            for (int i = 0; i < 4; i++)
#pragma unroll
                for (int j = 0; j < 4; j++) a[i][j] += rq[i] * rk[j];
        }
    }
    __syncthreads();   // all reads of Ks complete before Am overwrites it

#pragma unroll
    for (int i = 0; i < 4; i++)
#pragma unroll
        for (int j = 0; j < 4; j++) {
            int t = ty * 4 + i, s = tx * 4 + j;
            Am[t * 65 + s] = (s <= t) ? a[i][j] : 0.0f;
        }
    __syncthreads();

    // Phase 2: Y[t][p] = sum_s Am[t][s] * V[s][p] + sum_n Q[t][n] * Sp[p][n]
    float y[4][4];
#pragma unroll
    for (int i = 0; i < 4; i++)
#pragma unroll
        for (int j = 0; j < 4; j++) y[i][j] = 0.0f;
#pragma unroll 4
    for (int s = 0; s < 64; s++) {
        float ra[4], rv[4];
#pragma unroll
        for (int i = 0; i < 4; i++) ra[i] = Am[(ty * 4 + i) * 65 + s];
#pragma unroll
        for (int j = 0; j < 4; j++) rv[j] = Vs[s * 65 + tx * 4 + j];
#pragma unroll
        for (int i = 0; i < 4; i++)
#pragma unroll
            for (int j = 0; j < 4; j++) y[i][j] += ra[i] * rv[j];
    }
#pragma unroll 4
    for (int n = 0; n < 64; n++) {
        float rq[4], rs[4];
#pragma unroll
        for (int i = 0; i < 4; i++) rq[i] = Qs[(ty * 4 + i) * 65 + n];
#pragma unroll
        for (int j = 0; j < 4; j++) rs[j] = Sp[(tx * 4 + j) * 65 + n];
#pragma unroll
        for (int i = 0; i < 4; i++)
#pragma unroll
            for (int j = 0; j < 4; j++) y[i][j] += rq[i] * rs[j];
    }

    float* Yg = g_Y + ((size_t)bh * Tt + c * CH) * HDim;
#pragma unroll
    for (int i = 0; i < 4; i++)
#pragma unroll
        for (int j = 0; j < 4; j++)
            Yg[(ty * 4 + i) * 64 + tx * 4 + j] = y[i][j];
}

// ---------------------------------------------------------------------------
extern "C" void kernel_launch(void* const* d_in, const int* in_sizes, int n_in,
                              void* d_out, int out_size)
{
    const float* x  = (const float*)d_in[0];
    const float* Wq = (const float*)d_in[1];
    const float* bq = (const float*)d_in[2];
    const float* Wk = (const float*)d_in[3];
    const float* bk = (const float*)d_in[4];
    const float* Wv = (const float*)d_in[5];
    const float* bv = (const float*)d_in[6];
    const float* Wo = (const float*)d_in[7];
    const float* bo = (const float*)d_in[8];
    float* out = (float*)d_out;

    cudaFuncSetAttribute(tc_gemm, cudaFuncAttributeMaxDynamicSharedMemorySize, GEMM_SMEM);
    cudaFuncSetAttribute(attn_kernel, cudaFuncAttributeMaxDynamicSharedMemorySize, 4 * 64 * 65 * 4);

    // fused Q/K/V projections (z selects weight/bias/dst)
    tc_gemm<<<dim3(Dd / TN, BT / TM, 3), 256, GEMM_SMEM>>>(x, Wq, Wk, Wv, bq, bk, bv, nullptr, 0);
    chunk_sums<<<dim3(NCH, BHn), 64>>>();
    prefix_kernel<<<dim3(BHn, 16), 256>>>();
    attn_kernel<<<dim3(NCH, BHn), 256, 4 * 64 * 65 * 4>>>();
    tc_gemm<<<dim3(Dd / TN, BT / TM, 1), 256, GEMM_SMEM>>>(nullptr, Wo, nullptr, nullptr, bo, nullptr, nullptr, out, 1);
}

// round 11
// speedup vs baseline: 2.0551x; 1.3737x over previous
#include <cuda_runtime.h>
#include <cuda_fp16.h>
#include <cstdint>

// ---------------------------------------------------------------- problem dims
constexpr int Bb   = 2;
constexpr int Tt   = 2048;
constexpr int Dd   = 1024;
constexpr int Hh   = 16;
constexpr int HDim = 64;
constexpr int BT   = Bb * Tt;      // 4096
constexpr int BHn  = Bb * Hh;      // 32
constexpr int CH   = 64;           // chunk length (attention)
constexpr int NCH  = Tt / CH;      // 32

// ---------------------------------------------------------------- scratch
__device__ float g_Q[BHn * Tt * HDim];
__device__ float g_K[BHn * Tt * HDim];
__device__ float g_V[BHn * Tt * HDim];
__device__ float g_Y[BHn * Tt * HDim];
__device__ float g_cs[BHn * NCH * HDim * HDim];
__device__ float g_sp[BHn * NCH * HDim * HDim];

extern __shared__ char dyn_smem[];

// ---------------------------------------------------------------- helpers
// pack two floats to fp16x2: low half = lo_val, high half = hi_val
__device__ __forceinline__ uint32_t packh(float lo_val, float hi_val) {
    uint32_t r;
    asm("cvt.rn.f16x2.f32 %0, %1, %2;" : "=r"(r) : "f"(hi_val), "f"(lo_val));
    return r;
}
__device__ __forceinline__ float2 unpackh(uint32_t h) {
    __half2 hh = *reinterpret_cast<__half2*>(&h);
    return __half22float2(hh);
}

__device__ __forceinline__ void mma_f16(float* c, const uint32_t* a, const uint32_t* b) {
    asm volatile(
        "mma.sync.aligned.m16n8k16.row.col.f32.f16.f16.f32 "
        "{%0,%1,%2,%3}, {%4,%5,%6,%7}, {%8,%9}, {%0,%1,%2,%3};"
        : "+f"(c[0]), "+f"(c[1]), "+f"(c[2]), "+f"(c[3])
        : "r"(a[0]), "r"(a[1]), "r"(a[2]), "r"(a[3]), "r"(b[0]), "r"(b[1]));
}

__device__ __forceinline__ void ldmx4(uint32_t* r, uint32_t saddr) {
    asm volatile("ldmatrix.sync.aligned.m8n8.x4.shared.b16 {%0,%1,%2,%3}, [%4];"
                 : "=r"(r[0]), "=r"(r[1]), "=r"(r[2]), "=r"(r[3]) : "r"(saddr));
}

// ---------------------------------------------------------------- tc_gemm cfg
constexpr int TM = 128, TN = 128, KC = 32;   // CTA tile + K chunk (floats)
constexpr int NKC = Dd / KC;                 // 32
constexpr int PAD_K = 40;                    // fp16 row stride (conflict-free)
constexpr int TILE_B = 128 * PAD_K * 2;      // 10240 bytes per fp16 tile
constexpr int OFF_AHI = 0;
constexpr int OFF_ALO = TILE_B;
constexpr int OFF_BH  = 2 * TILE_B;
constexpr int BUF_B   = 3 * TILE_B;          // 30720 per stage
constexpr int GEMM_SMEM = 2 * BUF_B;         // 61440 (dynamic, double buffer)

// ---------------------------------------------------------------------------
// Tensor-core GEMM via mma.sync + ldmatrix, fp16 2-term split on A only:
//   out[m,n] = sum_k (Ah+Al)[m,k] * W16[n,k] + bias[n]
// mode 0: z = blockIdx.z selects Wq/Wk/Wv + bias, dst = g_Q/g_K/g_V head-major
// mode 1: W = Wo (w0), bias = b0, A gathered from g_Y head-major, dst = outp
// ---------------------------------------------------------------------------
__global__ __launch_bounds__(256) void tc_gemm(const float* __restrict__ Xsrc,
                                               const float* __restrict__ w0,
                                               const float* __restrict__ w1,
                                               const float* __restrict__ w2,
                                               const float* __restrict__ b0p,
                                               const float* __restrict__ b1p,
                                               const float* __restrict__ b2p,
                                               float* __restrict__ outp,
                                               int mode)
{
    char* smem = dyn_smem;
    const int tid  = threadIdx.x;
    const int wid  = tid >> 5;
    const int lane = tid & 31;
    const int z    = blockIdx.z;
    const int bn = blockIdx.x * TN;
    const int bm = blockIdx.y * TM;
    const float* W    = (z == 0) ? w0 : (z == 1) ? w1 : w2;
    const float* bias = (z == 0) ? b0p : (z == 1) ? b1p : b2p;

    uint32_t sbase;
    asm("{ .reg .u64 t; cvta.to.shared.u64 t, %1; cvt.u32.u64 %0, t; }"
        : "=r"(sbase) : "l"((const void*)smem));

    const int m0w = (wid >> 2) * 64;      // warp row offset
    const int n0w = (wid & 3) * 32;       // warp col offset
    const int lrow  = lane >> 2;
    const int lcol2 = (lane & 3) * 2;

    // ldmatrix per-lane base offsets (bytes)
    const uint32_t a_lane = (uint32_t)(((m0w + ((lane >> 3) & 1) * 8 + (lane & 7)) * PAD_K
                                        + (lane >> 4) * 8) * 2);
    const uint32_t b_lane = (uint32_t)(((n0w + (lane >> 4) * 8 + (lane & 7)) * PAD_K
                                        + ((lane >> 3) & 1) * 8) * 2);

    float c[4][4][4];
#pragma unroll
    for (int mi = 0; mi < 4; mi++)
#pragma unroll
        for (int ni = 0; ni < 4; ni++)
#pragma unroll
            for (int r = 0; r < 4; r++) c[mi][ni][r] = 0.0f;

    float4 pa[4], pb[4];

    // loader: fetch chunk k0 into pa/pb
    auto fetch = [&](int k0) {
#pragma unroll
        for (int t = 0; t < 4; t++) {
            int u = tid + t * 256, row = u >> 3, c4 = (u & 7) * 4;
            if (mode == 0) {
                pa[t] = *(const float4*)(Xsrc + (size_t)(bm + row) * Dd + k0 + c4);
            } else {
                int m = bm + row, b = m >> 11, tt = m & 2047;
                int k = k0 + c4, h = k >> 6, hd = k & 63;
                pa[t] = *(const float4*)(g_Y + (((size_t)(b * Hh + h) * Tt) + tt) * HDim + hd);
            }
            pb[t] = *(const float4*)(W + (size_t)(bn + row) * Dd + k0 + c4);
        }
    };
    // converter: A -> fp16 hi+lo, B -> single fp16, into buffer `bo`
    auto stash = [&](int bo) {
#pragma unroll
        for (int t = 0; t < 4; t++) {
            int u = tid + t * 256, row = u >> 3, c4 = (u & 7) * 4;
            int boff = bo + (row * PAD_K + c4) * 2;
            {
                float4 v = pa[t];
                uint32_t h01 = packh(v.x, v.y);
                uint32_t h23 = packh(v.z, v.w);
                float2 f01 = unpackh(h01), f23 = unpackh(h23);
                float lx = v.x - f01.x, ly = v.y - f01.y;
                float lz = v.z - f23.x, lw = v.w - f23.y;
                *(uint2*)(smem + OFF_AHI + boff) = make_uint2(h01, h23);
                *(uint2*)(smem + OFF_ALO + boff) = make_uint2(packh(lx, ly), packh(lz, lw));
            }
            {
                float4 v = pb[t];
                *(uint2*)(smem + OFF_BH + boff) = make_uint2(packh(v.x, v.y), packh(v.z, v.w));
            }
        }
    };

    // prologue: chunk 0 -> buf 0; prefetch chunk 1
    fetch(0);
    stash(0);
    fetch(KC);

    for (int ck = 0; ck < NKC; ck++) {
        __syncthreads();
        const uint32_t bo = (uint32_t)((ck & 1) * BUF_B);

        // ---- MMA phase on current buffer
#pragma unroll
        for (int kk = 0; kk < KC; kk += 16) {
            uint32_t ah[4][4], al[4][4];
#pragma unroll
            for (int mi = 0; mi < 4; mi++) {
                uint32_t ad = sbase + bo + OFF_AHI + a_lane + (uint32_t)((mi * 16 * PAD_K + kk) * 2);
                ldmx4(ah[mi], ad);
                ldmx4(al[mi], ad + (OFF_ALO - OFF_AHI));
            }
            uint32_t bh[4][2];
#pragma unroll
            for (int np = 0; np < 2; np++) {
                uint32_t bd = sbase + bo + OFF_BH + b_lane + (uint32_t)((np * 16 * PAD_K + kk) * 2);
                uint32_t r[4];
                ldmx4(r, bd);
                bh[np * 2][0] = r[0]; bh[np * 2][1] = r[1];
                bh[np * 2 + 1][0] = r[2]; bh[np * 2 + 1][1] = r[3];
            }
#pragma unroll
            for (int mi = 0; mi < 4; mi++)
#pragma unroll
                for (int ni = 0; ni < 4; ni++) {
                    mma_f16(c[mi][ni], ah[mi], bh[ni]);   // Ah*B
                    mma_f16(c[mi][ni], al[mi], bh[ni]);   // Al*B
                }
        }

        // ---- store chunk ck+1 into alternate buffer (under the MMAs)
        if (ck + 1 < NKC) stash(((ck + 1) & 1) * BUF_B);
        // ---- prefetch chunk ck+2
        if (ck + 2 < NKC) fetch((ck + 2) * KC);
    }

    // ---- epilogue
#pragma unroll
    for (int mi = 0; mi < 4; mi++) {
        int row0 = bm + m0w + mi * 16 + lrow;
        int row1 = row0 + 8;
#pragma unroll
        for (int ni = 0; ni < 4; ni++) {
            int n = bn + n0w + ni * 8 + lcol2;
            float bb0 = bias[n], bb1 = bias[n + 1];
            float2 v0 = make_float2(c[mi][ni][0] + bb0, c[mi][ni][1] + bb1);
            float2 v1 = make_float2(c[mi][ni][2] + bb0, c[mi][ni][3] + bb1);
            if (mode == 0) {
                float* base = (z == 0) ? g_Q : (z == 1) ? g_K : g_V;
                int h = n >> 6, hd = n & 63;
                int batch0 = row0 >> 11, t0 = row0 & 2047;
                int batch1 = row1 >> 11, t1 = row1 & 2047;
                *(float2*)(base + (((size_t)(batch0 * Hh + h) * Tt) + t0) * HDim + hd) = v0;
                *(float2*)(base + (((size_t)(batch1 * Hh + h) * Tt) + t1) * HDim + hd) = v1;
            } else {
                *(float2*)(outp + (size_t)row0 * Dd + n) = v0;
                *(float2*)(outp + (size_t)row1 * Dd + n) = v1;
            }
        }
    }
}

// ---------------------------------------------------------------------------
// Per-chunk state sums: M[p,n] = sum_{t in chunk} V[t,p] * K[t,n]
// 64 threads, 8x8 microtile.
// ---------------------------------------------------------------------------
__global__ __launch_bounds__(64) void chunk_sums()
{
    __shared__ float Ks[64 * 64];
    __shared__ float Vs[64 * 64];
    const int bh = blockIdx.y, c = blockIdx.x;
    const int tid = threadIdx.x;
    const float* Kg = g_K + ((size_t)bh * Tt + c * CH) * HDim;
    const float* Vg = g_V + ((size_t)bh * Tt + c * CH) * HDim;
    for (int i = tid; i < 1024; i += 64) {
        ((float4*)Ks)[i] = ((const float4*)Kg)[i];
        ((float4*)Vs)[i] = ((const float4*)Vg)[i];
    }
    __syncthreads();
    const int tx = tid & 7, ty = tid >> 3;
    float acc[8][8];
#pragma unroll
    for (int i = 0; i < 8; i++)
#pragma unroll
        for (int j = 0; j < 8; j++) acc[i][j] = 0.0f;
#pragma unroll 4
    for (int t = 0; t < 64; t++) {
        float rv[8], rk[8];
        *(float4*)(rv)     = *(const float4*)(Vs + t * 64 + ty * 8);
        *(float4*)(rv + 4) = *(const float4*)(Vs + t * 64 + ty * 8 + 4);
        *(float4*)(rk)     = *(const float4*)(Ks + t * 64 + tx * 8);
        *(float4*)(rk + 4) = *(const float4*)(Ks + t * 64 + tx * 8 + 4);
#pragma unroll
        for (int i = 0; i < 8; i++)
#pragma unroll
            for (int j = 0; j < 8; j++) acc[i][j] += rv[i] * rk[j];
    }
    float* dst = g_cs + ((size_t)bh * NCH + c) * 4096;
#pragma unroll
    for (int i = 0; i < 8; i++)
#pragma unroll
        for (int j = 0; j < 8; j += 4)
            *(float4*)(dst + (ty * 8 + i) * 64 + tx * 8 + j) =
                make_float4(acc[i][j], acc[i][j + 1], acc[i][j + 2], acc[i][j + 3]);
}

// ---------------------------------------------------------------------------
// Exclusive prefix over chunks (parallelized: 512 blocks)
// ---------------------------------------------------------------------------
__global__ __launch_bounds__(256) void prefix_kernel()
{
    const int bh = blockIdx.x;
    const int e = blockIdx.y * 256 + threadIdx.x;
    float acc = 0.0f;
#pragma unroll
    for (int c = 0; c < NCH; c++) {
        size_t off = ((size_t)bh * NCH + c) * 4096 + e;
        g_sp[off] = acc;
        acc += g_cs[off];
    }
}

// ---------------------------------------------------------------------------
// Intra-chunk attention + inter-chunk state term.
// Transposed smem layouts (pad 68 = float4-aligned rows) so ALL inner-loop
// operands are LDS.128. 4 tiles, Amt aliases Kt after phase 1.
//   Qt[n][t], Kt[n][s] (-> Amt[s][t]), Vs[s][p], Spt[n][p]
// ---------------------------------------------------------------------------
constexpr int APAD = 68;
constexpr int ATTN_SMEM = 4 * 64 * APAD * 4;   // 69632 B

__global__ __launch_bounds__(256) void attn_kernel()
{
    float* Qt  = (float*)dyn_smem;     // [n][t]
    float* Kt  = Qt + 64 * APAD;       // [n][s]
    float* Vs  = Kt + 64 * APAD;       // [s][p]
    float* Spt = Vs + 64 * APAD;       // [n][p]
    float* Amt = Kt;                   // [s][t], overwrites Kt in phase 2
    const int bh = blockIdx.y, c = blockIdx.x;
    const int tid = threadIdx.x;
    const float* Qg = g_Q + ((size_t)bh * Tt + c * CH) * HDim;
    const float* Kg = g_K + ((size_t)bh * Tt + c * CH) * HDim;
    const float* Vg = g_V + ((size_t)bh * Tt + c * CH) * HDim;
    const float* Sg = g_sp + ((size_t)bh * NCH + c) * 4096;

    for (int i = tid; i < 1024; i += 256) {
        int r = i >> 4;               // row in gmem tile (t / s / p-row)
        int c4 = (i & 15) << 2;       // col base (n / p)
        float4 q = *(const float4*)(Qg + r * 64 + c4);
        float4 k = *(const float4*)(Kg + r * 64 + c4);
        float4 v = *(const float4*)(Vg + r * 64 + c4);
        float4 s = *(const float4*)(Sg + r * 64 + c4);
        // transpose Q, K: [t][n] -> [n][t]
        Qt[(c4 + 0) * APAD + r] = q.x; Qt[(c4 + 1) * APAD + r] = q.y;
        Qt[(c4 + 2) * APAD + r] = q.z; Qt[(c4 + 3) * APAD + r] = q.w;
        Kt[(c4 + 0) * APAD + r] = k.x; Kt[(c4 + 1) * APAD + r] = k.y;
        Kt[(c4 + 2) * APAD + r] = k.z; Kt[(c4 + 3) * APAD + r] = k.w;
        // V row-major [s][p]
        *(float4*)(Vs + r * APAD + c4) = v;
        // transpose Sp: gmem [p][n] -> smem [n][p]
        Spt[(c4 + 0) * APAD + r] = s.x; Spt[(c4 + 1) * APAD + r] = s.y;
        Spt[(c4 + 2) * APAD + r] = s.z; Spt[(c4 + 3) * APAD + r] = s.w;
    }
    __syncthreads();

    const int tx = tid & 15, ty = tid >> 4;

    // Phase 1: a[i][j] = sum_n Q[t=ty4+i][n] * K[s=tx4+j][n]   (regs)
    float a[4][4];
#pragma unroll
    for (int i = 0; i < 4; i++)
#pragma unroll
        for (int j = 0; j < 4; j++) a[i][j] = 0.0f;
#pragma unroll 4
    for (int n = 0; n < 64; n++) {
        float4 rq = *(const float4*)(Qt + n * APAD + ty * 4);
        float4 rk = *(const float4*)(Kt + n * APAD + tx * 4);
        float q_[4] = {rq.x, rq.y, rq.z, rq.w};
        float k_[4] = {rk.x, rk.y, rk.z, rk.w};
#pragma unroll
        for (int i = 0; i < 4; i++)
#pragma unroll
            for (int j = 0; j < 4; j++) a[i][j] += q_[i] * k_[j];
    }
    __syncthreads();   // all Kt reads done before Amt overwrites

    // write masked scores TRANSPOSED: Amt[s][t]
#pragma unroll
    for (int i = 0; i < 4; i++)
#pragma unroll
        for (int j = 0; j < 4; j++) {
            int t = ty * 4 + i, s = tx * 4 + j;
            Amt[s * APAD + t] = (s <= t) ? a[i][j] : 0.0f;
        }
    __syncthreads();

    // Phase 2: Y[t][p] = sum_s Amt[s][t] * Vs[s][p] + sum_n Qt[n][t] * Spt[n][p]
    float y[4][4];
#pragma unroll
    for (int i = 0; i < 4; i++)
#pragma unroll
        for (int j = 0; j < 4; j++) y[i][j] = 0.0f;
#pragma unroll 4
    for (int s = 0; s < 64; s++) {
        float4 ra = *(const float4*)(Amt + s * APAD + ty * 4);
        float4 rv = *(const float4*)(Vs + s * APAD + tx * 4);
        float a_[4] = {ra.x, ra.y, ra.z, ra.w};
        float v_[4] = {rv.x, rv.y, rv.z, rv.w};
#pragma unroll
        for (int i = 0; i < 4; i++)
#pragma unroll
            for (int j = 0; j < 4; j++) y[i][j] += a_[i] * v_[j];
    }
#pragma unroll 4
    for (int n = 0; n < 64; n++) {
        float4 rq = *(const float4*)(Qt + n * APAD + ty * 4);
        float4 rs = *(const float4*)(Spt + n * APAD + tx * 4);
        float q_[4] = {rq.x, rq.y, rq.z, rq.w};
        float s_[4] = {rs.x, rs.y, rs.z, rs.w};
#pragma unroll
        for (int i = 0; i < 4; i++)
#pragma unroll
            for (int j = 0; j < 4; j++) y[i][j] += q_[i] * s_[j];
    }

    float* Yg = g_Y + ((size_t)bh * Tt + c * CH) * HDim;
#pragma unroll
    for (int i = 0; i < 4; i++)
        *(float4*)(Yg + (ty * 4 + i) * 64 + tx * 4) =
            make_float4(y[i][0], y[i][1], y[i][2], y[i][3]);
}

// ---------------------------------------------------------------------------
extern "C" void kernel_launch(void* const* d_in, const int* in_sizes, int n_in,
                              void* d_out, int out_size)
{
    const float* x  = (const float*)d_in[0];
    const float* Wq = (const float*)d_in[1];
    const float* bq = (const float*)d_in[2];
    const float* Wk = (const float*)d_in[3];
    const float* bk = (const float*)d_in[4];
    const float* Wv = (const float*)d_in[5];
    const float* bv = (const float*)d_in[6];
    const float* Wo = (const float*)d_in[7];
    const float* bo = (const float*)d_in[8];
    float* out = (float*)d_out;

    cudaFuncSetAttribute(tc_gemm, cudaFuncAttributeMaxDynamicSharedMemorySize, GEMM_SMEM);
    cudaFuncSetAttribute(attn_kernel, cudaFuncAttributeMaxDynamicSharedMemorySize, ATTN_SMEM);

    // fused Q/K/V projections (z selects weight/bias/dst)
    tc_gemm<<<dim3(Dd / TN, BT / TM, 3), 256, GEMM_SMEM>>>(x, Wq, Wk, Wv, bq, bk, bv, nullptr, 0);
    chunk_sums<<<dim3(NCH, BHn), 64>>>();
    prefix_kernel<<<dim3(BHn, 16), 256>>>();
    attn_kernel<<<dim3(NCH, BHn), 256, ATTN_SMEM>>>();
    tc_gemm<<<dim3(Dd / TN, BT / TM, 1), 256, GEMM_SMEM>>>(nullptr, Wo, nullptr, nullptr, bo, nullptr, nullptr, out, 1);
}

// round 12
// speedup vs baseline: 2.3023x; 1.1203x over previous
#include <cuda_runtime.h>
#include <cuda_fp16.h>
#include <cstdint>

// ---------------------------------------------------------------- problem dims
constexpr int Bb   = 2;
constexpr int Tt   = 2048;
constexpr int Dd   = 1024;
constexpr int Hh   = 16;
constexpr int HDim = 64;
constexpr int BT   = Bb * Tt;      // 4096
constexpr int BHn  = Bb * Hh;      // 32
constexpr int CH   = 64;           // chunk length (attention)
constexpr int NCH  = Tt / CH;      // 32

// ---------------------------------------------------------------- scratch
__device__ float g_Q[BHn * Tt * HDim];
__device__ float g_K[BHn * Tt * HDim];
__device__ float g_V[BHn * Tt * HDim];
__device__ float g_Y[BHn * Tt * HDim];
__device__ float g_cs[BHn * NCH * HDim * HDim];
__device__ float g_sp[BHn * NCH * HDim * HDim];

extern __shared__ char dyn_smem[];

// ---------------------------------------------------------------- helpers
// pack two floats to fp16x2: low half = lo_val, high half = hi_val
__device__ __forceinline__ uint32_t packh(float lo_val, float hi_val) {
    uint32_t r;
    asm("cvt.rn.f16x2.f32 %0, %1, %2;" : "=r"(r) : "f"(hi_val), "f"(lo_val));
    return r;
}
__device__ __forceinline__ float2 unpackh(uint32_t h) {
    __half2 hh = *reinterpret_cast<__half2*>(&h);
    return __half22float2(hh);
}

__device__ __forceinline__ void mma_f16(float* c, const uint32_t* a, const uint32_t* b) {
    asm volatile(
        "mma.sync.aligned.m16n8k16.row.col.f32.f16.f16.f32 "
        "{%0,%1,%2,%3}, {%4,%5,%6,%7}, {%8,%9}, {%0,%1,%2,%3};"
        : "+f"(c[0]), "+f"(c[1]), "+f"(c[2]), "+f"(c[3])
        : "r"(a[0]), "r"(a[1]), "r"(a[2]), "r"(a[3]), "r"(b[0]), "r"(b[1]));
}

__device__ __forceinline__ void ldmx4(uint32_t* r, uint32_t saddr) {
    asm volatile("ldmatrix.sync.aligned.m8n8.x4.shared.b16 {%0,%1,%2,%3}, [%4];"
                 : "=r"(r[0]), "=r"(r[1]), "=r"(r[2]), "=r"(r[3]) : "r"(saddr));
}

// ---------------------------------------------------------------- tc_gemm cfg
constexpr int TM = 128, TN = 128, KC = 32;   // CTA tile + K chunk (floats)
constexpr int NKC = Dd / KC;                 // 32
constexpr int PAD_K = 40;                    // fp16 row stride (conflict-free)
constexpr int TILE_B = 128 * PAD_K * 2;      // 10240 bytes per fp16 tile
constexpr int OFF_AHI = 0;
constexpr int OFF_ALO = TILE_B;
constexpr int OFF_BH  = 2 * TILE_B;
constexpr int BUF_B   = 3 * TILE_B;          // 30720 per stage
constexpr int GEMM_SMEM = 2 * BUF_B;         // 61440 (dynamic, double buffer)

// ---------------------------------------------------------------------------
// Tensor-core GEMM via mma.sync + ldmatrix, fp16 2-term split on A only:
//   out[m,n] = sum_k (Ah+Al)[m,k] * W16[n,k] + bias[n]
// mode 0: z = blockIdx.z selects Wq/Wk/Wv + bias, dst = g_Q/g_K/g_V head-major
// mode 1: W = Wo (w0), bias = b0, A gathered from g_Y head-major, dst = outp
// ---------------------------------------------------------------------------
__global__ __launch_bounds__(256) void tc_gemm(const float* __restrict__ Xsrc,
                                               const float* __restrict__ w0,
                                               const float* __restrict__ w1,
                                               const float* __restrict__ w2,
                                               const float* __restrict__ b0p,
                                               const float* __restrict__ b1p,
                                               const float* __restrict__ b2p,
                                               float* __restrict__ outp,
                                               int mode)
{
    char* smem = dyn_smem;
    const int tid  = threadIdx.x;
    const int wid  = tid >> 5;
    const int lane = tid & 31;
    const int z    = blockIdx.z;
    const int bn = blockIdx.x * TN;
    const int bm = blockIdx.y * TM;
    const float* W    = (z == 0) ? w0 : (z == 1) ? w1 : w2;
    const float* bias = (z == 0) ? b0p : (z == 1) ? b1p : b2p;

    uint32_t sbase;
    asm("{ .reg .u64 t; cvta.to.shared.u64 t, %1; cvt.u32.u64 %0, t; }"
        : "=r"(sbase) : "l"((const void*)smem));

    const int m0w = (wid >> 2) * 64;      // warp row offset
    const int n0w = (wid & 3) * 32;       // warp col offset
    const int lrow  = lane >> 2;
    const int lcol2 = (lane & 3) * 2;

    // ldmatrix per-lane base offsets (bytes)
    const uint32_t a_lane = (uint32_t)(((m0w + ((lane >> 3) & 1) * 8 + (lane & 7)) * PAD_K
                                        + (lane >> 4) * 8) * 2);
    const uint32_t b_lane = (uint32_t)(((n0w + (lane >> 4) * 8 + (lane & 7)) * PAD_K
                                        + ((lane >> 3) & 1) * 8) * 2);

    float c[4][4][4];
#pragma unroll
    for (int mi = 0; mi < 4; mi++)
#pragma unroll
        for (int ni = 0; ni < 4; ni++)
#pragma unroll
            for (int r = 0; r < 4; r++) c[mi][ni][r] = 0.0f;

    float4 pa[4], pb[4];

    // loader: fetch chunk k0 into pa/pb
    auto fetch = [&](int k0) {
#pragma unroll
        for (int t = 0; t < 4; t++) {
            int u = tid + t * 256, row = u >> 3, c4 = (u & 7) * 4;
            if (mode == 0) {
                pa[t] = *(const float4*)(Xsrc + (size_t)(bm + row) * Dd + k0 + c4);
            } else {
                int m = bm + row, b = m >> 11, tt = m & 2047;
                int k = k0 + c4, h = k >> 6, hd = k & 63;
                pa[t] = *(const float4*)(g_Y + (((size_t)(b * Hh + h) * Tt) + tt) * HDim + hd);
            }
            pb[t] = *(const float4*)(W + (size_t)(bn + row) * Dd + k0 + c4);
        }
    };
    // converter: A -> fp16 hi+lo, B -> single fp16, into buffer `bo`
    auto stash = [&](int bo) {
#pragma unroll
        for (int t = 0; t < 4; t++) {
            int u = tid + t * 256, row = u >> 3, c4 = (u & 7) * 4;
            int boff = bo + (row * PAD_K + c4) * 2;
            {
                float4 v = pa[t];
                uint32_t h01 = packh(v.x, v.y);
                uint32_t h23 = packh(v.z, v.w);
                float2 f01 = unpackh(h01), f23 = unpackh(h23);
                float lx = v.x - f01.x, ly = v.y - f01.y;
                float lz = v.z - f23.x, lw = v.w - f23.y;
                *(uint2*)(smem + OFF_AHI + boff) = make_uint2(h01, h23);
                *(uint2*)(smem + OFF_ALO + boff) = make_uint2(packh(lx, ly), packh(lz, lw));
            }
            {
                float4 v = pb[t];
                *(uint2*)(smem + OFF_BH + boff) = make_uint2(packh(v.x, v.y), packh(v.z, v.w));
            }
        }
    };

    // prologue: chunk 0 -> buf 0; prefetch chunk 1
    fetch(0);
    stash(0);
    fetch(KC);

    for (int ck = 0; ck < NKC; ck++) {
        __syncthreads();
        const uint32_t bo = (uint32_t)((ck & 1) * BUF_B);

        // ---- MMA phase on current buffer
#pragma unroll
        for (int kk = 0; kk < KC; kk += 16) {
            uint32_t ah[4][4], al[4][4];
#pragma unroll
            for (int mi = 0; mi < 4; mi++) {
                uint32_t ad = sbase + bo + OFF_AHI + a_lane + (uint32_t)((mi * 16 * PAD_K + kk) * 2);
                ldmx4(ah[mi], ad);
                ldmx4(al[mi], ad + (OFF_ALO - OFF_AHI));
            }
            uint32_t bh[4][2];
#pragma unroll
            for (int np = 0; np < 2; np++) {
                uint32_t bd = sbase + bo + OFF_BH + b_lane + (uint32_t)((np * 16 * PAD_K + kk) * 2);
                uint32_t r[4];
                ldmx4(r, bd);
                bh[np * 2][0] = r[0]; bh[np * 2][1] = r[1];
                bh[np * 2 + 1][0] = r[2]; bh[np * 2 + 1][1] = r[3];
            }
#pragma unroll
            for (int mi = 0; mi < 4; mi++)
#pragma unroll
                for (int ni = 0; ni < 4; ni++) {
                    mma_f16(c[mi][ni], ah[mi], bh[ni]);   // Ah*B
                    mma_f16(c[mi][ni], al[mi], bh[ni]);   // Al*B
                }
        }

        // ---- store chunk ck+1 into alternate buffer (under the MMAs)
        if (ck + 1 < NKC) stash(((ck + 1) & 1) * BUF_B);
        // ---- prefetch chunk ck+2
        if (ck + 2 < NKC) fetch((ck + 2) * KC);
    }

    // ---- epilogue
#pragma unroll
    for (int mi = 0; mi < 4; mi++) {
        int row0 = bm + m0w + mi * 16 + lrow;
        int row1 = row0 + 8;
#pragma unroll
        for (int ni = 0; ni < 4; ni++) {
            int n = bn + n0w + ni * 8 + lcol2;
            float bb0 = bias[n], bb1 = bias[n + 1];
            float2 v0 = make_float2(c[mi][ni][0] + bb0, c[mi][ni][1] + bb1);
            float2 v1 = make_float2(c[mi][ni][2] + bb0, c[mi][ni][3] + bb1);
            if (mode == 0) {
                float* base = (z == 0) ? g_Q : (z == 1) ? g_K : g_V;
                int h = n >> 6, hd = n & 63;
                int batch0 = row0 >> 11, t0 = row0 & 2047;
                int batch1 = row1 >> 11, t1 = row1 & 2047;
                *(float2*)(base + (((size_t)(batch0 * Hh + h) * Tt) + t0) * HDim + hd) = v0;
                *(float2*)(base + (((size_t)(batch1 * Hh + h) * Tt) + t1) * HDim + hd) = v1;
            } else {
                *(float2*)(outp + (size_t)row0 * Dd + n) = v0;
                *(float2*)(outp + (size_t)row1 * Dd + n) = v1;
            }
        }
    }
}

// ---------------------------------------------------------------------------
// Per-chunk state sums: M[p,n] = sum_{t in chunk} V[t,p] * K[t,n]
// 64 threads, 8x8 microtile.
// ---------------------------------------------------------------------------
__global__ __launch_bounds__(64) void chunk_sums()
{
    __shared__ float Ks[64 * 64];
    __shared__ float Vs[64 * 64];
    const int bh = blockIdx.y, c = blockIdx.x;
    const int tid = threadIdx.x;
    const float* Kg = g_K + ((size_t)bh * Tt + c * CH) * HDim;
    const float* Vg = g_V + ((size_t)bh * Tt + c * CH) * HDim;
    for (int i = tid; i < 1024; i += 64) {
        ((float4*)Ks)[i] = ((const float4*)Kg)[i];
        ((float4*)Vs)[i] = ((const float4*)Vg)[i];
    }
    __syncthreads();
    const int tx = tid & 7, ty = tid >> 3;
    float acc[8][8];
#pragma unroll
    for (int i = 0; i < 8; i++)
#pragma unroll
        for (int j = 0; j < 8; j++) acc[i][j] = 0.0f;
#pragma unroll 4
    for (int t = 0; t < 64; t++) {
        float rv[8], rk[8];
        *(float4*)(rv)     = *(const float4*)(Vs + t * 64 + ty * 8);
        *(float4*)(rv + 4) = *(const float4*)(Vs + t * 64 + ty * 8 + 4);
        *(float4*)(rk)     = *(const float4*)(Ks + t * 64 + tx * 8);
        *(float4*)(rk + 4) = *(const float4*)(Ks + t * 64 + tx * 8 + 4);
#pragma unroll
        for (int i = 0; i < 8; i++)
#pragma unroll
            for (int j = 0; j < 8; j++) acc[i][j] += rv[i] * rk[j];
    }
    float* dst = g_cs + ((size_t)bh * NCH + c) * 4096;
#pragma unroll
    for (int i = 0; i < 8; i++)
#pragma unroll
        for (int j = 0; j < 8; j += 4)
            *(float4*)(dst + (ty * 8 + i) * 64 + tx * 8 + j) =
                make_float4(acc[i][j], acc[i][j + 1], acc[i][j + 2], acc[i][j + 3]);
}

// ---------------------------------------------------------------------------
// Exclusive prefix over chunks (parallelized: 512 blocks)
// ---------------------------------------------------------------------------
__global__ __launch_bounds__(256) void prefix_kernel()
{
    const int bh = blockIdx.x;
    const int e = blockIdx.y * 256 + threadIdx.x;
    float acc = 0.0f;
#pragma unroll
    for (int c = 0; c < NCH; c++) {
        size_t off = ((size_t)bh * NCH + c) * 4096 + e;
        g_sp[off] = acc;
        acc += g_cs[off];
    }
}

// ---------------------------------------------------------------------------
// Tensor-core intra-chunk attention:
//   scores A[t][s] = mask(Q[t]·K[s]);  Y[t][p] = A·V + Q·Sp^T
// fp16 with 2-term split on left operands (Q, Am); K/V/Sp single fp16.
// Warp grid 4x2: warp w covers rows mw=(w>>1)*16, cols nw=(w&1)*32.
// smem tiles fp16 [64][TPAD]: Qh, Ql, K, Vt (V transposed), Sp, Amh, Aml.
// ---------------------------------------------------------------------------
constexpr int TPAD = 72;                     // fp16 elems/row; 144B stride -> conflict-free ldmatrix
constexpr int T_TILE2 = 64 * TPAD * 2;       // 9216 B
constexpr int OFF_QH2 = 0;
constexpr int OFF_QL2 = 1 * T_TILE2;
constexpr int OFF_K2  = 2 * T_TILE2;
constexpr int OFF_VT2 = 3 * T_TILE2;
constexpr int OFF_SP2 = 4 * T_TILE2;
constexpr int OFF_AH2 = 5 * T_TILE2;
constexpr int OFF_AL2 = 6 * T_TILE2;
constexpr int ATTN_SMEM = 7 * T_TILE2;       // 64512 B

__global__ __launch_bounds__(256) void attn_tc()
{
    char* smem = dyn_smem;
    uint32_t sbase;
    asm("{ .reg .u64 t; cvta.to.shared.u64 t, %1; cvt.u32.u64 %0, t; }"
        : "=r"(sbase) : "l"((const void*)smem));
    const int bh = blockIdx.y, c = blockIdx.x;
    const int tid = threadIdx.x;
    const int wid = tid >> 5;
    const int lane = tid & 31;
    const float* Qg = g_Q + ((size_t)bh * Tt + c * CH) * HDim;
    const float* Kg = g_K + ((size_t)bh * Tt + c * CH) * HDim;
    const float* Vg = g_V + ((size_t)bh * Tt + c * CH) * HDim;
    const float* Sg = g_sp + ((size_t)bh * NCH + c) * 4096;

    __half* sQh = (__half*)(smem + OFF_QH2);
    __half* sQl = (__half*)(smem + OFF_QL2);
    __half* sK  = (__half*)(smem + OFF_K2);
    __half* sVt = (__half*)(smem + OFF_VT2);
    __half* sSp = (__half*)(smem + OFF_SP2);
    __half* sAh = (__half*)(smem + OFF_AH2);
    __half* sAl = (__half*)(smem + OFF_AL2);

    // ---- load + convert
    for (int i = tid; i < 1024; i += 256) {
        int r = i >> 4;               // row 0..63
        int c4 = (i & 15) << 2;       // col base
        float4 q = *(const float4*)(Qg + r * 64 + c4);
        float4 k = *(const float4*)(Kg + r * 64 + c4);
        float4 v = *(const float4*)(Vg + r * 64 + c4);
        float4 s = *(const float4*)(Sg + r * 64 + c4);
        // Q hi/lo
        uint32_t h01 = packh(q.x, q.y), h23 = packh(q.z, q.w);
        float2 f01 = unpackh(h01), f23 = unpackh(h23);
        *(uint2*)(sQh + r * TPAD + c4) = make_uint2(h01, h23);
        *(uint2*)(sQl + r * TPAD + c4) =
            make_uint2(packh(q.x - f01.x, q.y - f01.y), packh(q.z - f23.x, q.w - f23.y));
        // K single fp16
        *(uint2*)(sK + r * TPAD + c4) = make_uint2(packh(k.x, k.y), packh(k.z, k.w));
        // V transposed: sVt[p][s], p = c4+i, s = r
        sVt[(c4 + 0) * TPAD + r] = __float2half(v.x);
        sVt[(c4 + 1) * TPAD + r] = __float2half(v.y);
        sVt[(c4 + 2) * TPAD + r] = __float2half(v.z);
        sVt[(c4 + 3) * TPAD + r] = __float2half(v.w);
        // Sp[p][n] single fp16 (gmem already [p][n])
        *(uint2*)(sSp + r * TPAD + c4) = make_uint2(packh(s.x, s.y), packh(s.z, s.w));
    }
    __syncthreads();

    const int mw = (wid >> 1) * 16;       // warp M (t) base
    const int nw = (wid & 1) * 32;        // warp N (s / p) base
    const int lrow  = lane >> 2;
    const int lcol2 = (lane & 3) * 2;

    const uint32_t a_lane = (uint32_t)(((mw + ((lane >> 3) & 1) * 8 + (lane & 7)) * TPAD
                                        + (lane >> 4) * 8) * 2);
    const uint32_t b_lane = (uint32_t)(((nw + (lane >> 4) * 8 + (lane & 7)) * TPAD
                                        + ((lane >> 3) & 1) * 8) * 2);

    // ---- phase 1: scores a[ni][r] over C[t][s]
    float a[4][4];
#pragma unroll
    for (int ni = 0; ni < 4; ni++)
#pragma unroll
        for (int r = 0; r < 4; r++) a[ni][r] = 0.0f;
#pragma unroll
    for (int kk = 0; kk < 64; kk += 16) {
        uint32_t qh[4], ql[4];
        uint32_t ad = sbase + OFF_QH2 + a_lane + (uint32_t)(kk * 2);
        ldmx4(qh, ad);
        ldmx4(ql, ad + (OFF_QL2 - OFF_QH2));
        uint32_t bk[4][2];
#pragma unroll
        for (int np = 0; np < 2; np++) {
            uint32_t r4[4];
            ldmx4(r4, sbase + OFF_K2 + b_lane + (uint32_t)((np * 16 * TPAD + kk) * 2));
            bk[np * 2][0] = r4[0]; bk[np * 2][1] = r4[1];
            bk[np * 2 + 1][0] = r4[2]; bk[np * 2 + 1][1] = r4[3];
        }
#pragma unroll
        for (int ni = 0; ni < 4; ni++) {
            mma_f16(a[ni], qh, bk[ni]);
            mma_f16(a[ni], ql, bk[ni]);
        }
    }

    // ---- write masked scores (hi/lo split) to sAh/sAl
#pragma unroll
    for (int ni = 0; ni < 4; ni++)
#pragma unroll
        for (int r = 0; r < 4; r++) {
            int t = mw + lrow + (r >> 1) * 8;
            int s = nw + ni * 8 + lcol2 + (r & 1);
            float v = (s <= t) ? a[ni][r] : 0.0f;
            __half h = __float2half(v);
            sAh[t * TPAD + s] = h;
            sAl[t * TPAD + s] = __float2half(v - __half2float(h));
        }

    // ---- phase 2b first (independent of Am): y += Q·Sp^T
    float y[4][4];
#pragma unroll
    for (int ni = 0; ni < 4; ni++)
#pragma unroll
        for (int r = 0; r < 4; r++) y[ni][r] = 0.0f;
#pragma unroll
    for (int kk = 0; kk < 64; kk += 16) {
        uint32_t qh[4], ql[4];
        uint32_t ad = sbase + OFF_QH2 + a_lane + (uint32_t)(kk * 2);
        ldmx4(qh, ad);
        ldmx4(ql, ad + (OFF_QL2 - OFF_QH2));
        uint32_t bs[4][2];
#pragma unroll
        for (int np = 0; np < 2; np++) {
            uint32_t r4[4];
            ldmx4(r4, sbase + OFF_SP2 + b_lane + (uint32_t)((np * 16 * TPAD + kk) * 2));
            bs[np * 2][0] = r4[0]; bs[np * 2][1] = r4[1];
            bs[np * 2 + 1][0] = r4[2]; bs[np * 2 + 1][1] = r4[3];
        }
#pragma unroll
        for (int ni = 0; ni < 4; ni++) {
            mma_f16(y[ni], qh, bs[ni]);
            mma_f16(y[ni], ql, bs[ni]);
        }
    }

    __syncthreads();   // Am published by all warps

    // ---- phase 2a: y += Am·V  (A = Amh+Aml over s; B = Vt[p][s])
#pragma unroll
    for (int kk = 0; kk < 64; kk += 16) {
        uint32_t amh[4], aml[4];
        uint32_t ad = sbase + OFF_AH2 + a_lane + (uint32_t)(kk * 2);
        ldmx4(amh, ad);
        ldmx4(aml, ad + (OFF_AL2 - OFF_AH2));
        uint32_t bv[4][2];
#pragma unroll
        for (int np = 0; np < 2; np++) {
            uint32_t r4[4];
            ldmx4(r4, sbase + OFF_VT2 + b_lane + (uint32_t)((np * 16 * TPAD + kk) * 2));
            bv[np * 2][0] = r4[0]; bv[np * 2][1] = r4[1];
            bv[np * 2 + 1][0] = r4[2]; bv[np * 2 + 1][1] = r4[3];
        }
#pragma unroll
        for (int ni = 0; ni < 4; ni++) {
            mma_f16(y[ni], amh, bv[ni]);
            mma_f16(y[ni], aml, bv[ni]);
        }
    }

    // ---- epilogue: Y[t][p] fp32
    float* Yg = g_Y + ((size_t)bh * Tt + c * CH) * HDim;
#pragma unroll
    for (int ni = 0; ni < 4; ni++) {
        int p = nw + ni * 8 + lcol2;
        int t0 = mw + lrow, t1 = t0 + 8;
        *(float2*)(Yg + t0 * 64 + p) = make_float2(y[ni][0], y[ni][1]);
        *(float2*)(Yg + t1 * 64 + p) = make_float2(y[ni][2], y[ni][3]);
    }
}

// ---------------------------------------------------------------------------
extern "C" void kernel_launch(void* const* d_in, const int* in_sizes, int n_in,
                              void* d_out, int out_size)
{
    const float* x  = (const float*)d_in[0];
    const float* Wq = (const float*)d_in[1];
    const float* bq = (const float*)d_in[2];
    const float* Wk = (const float*)d_in[3];
    const float* bk = (const float*)d_in[4];
    const float* Wv = (const float*)d_in[5];
    const float* bv = (const float*)d_in[6];
    const float* Wo = (const float*)d_in[7];
    const float* bo = (const float*)d_in[8];
    float* out = (float*)d_out;

    cudaFuncSetAttribute(tc_gemm, cudaFuncAttributeMaxDynamicSharedMemorySize, GEMM_SMEM);
    cudaFuncSetAttribute(attn_tc, cudaFuncAttributeMaxDynamicSharedMemorySize, ATTN_SMEM);

    // fused Q/K/V projections (z selects weight/bias/dst)
    tc_gemm<<<dim3(Dd / TN, BT / TM, 3), 256, GEMM_SMEM>>>(x, Wq, Wk, Wv, bq, bk, bv, nullptr, 0);
    chunk_sums<<<dim3(NCH, BHn), 64>>>();
    prefix_kernel<<<dim3(BHn, 16), 256>>>();
    attn_tc<<<dim3(NCH, BHn), 256, ATTN_SMEM>>>();
    tc_gemm<<<dim3(Dd / TN, BT / TM, 1), 256, GEMM_SMEM>>>(nullptr, Wo, nullptr, nullptr, bo, nullptr, nullptr, out, 1);
}

// round 13
// speedup vs baseline: 3.0255x; 1.3141x over previous
#include <cuda_runtime.h>
#include <cuda_fp16.h>
#include <cstdint>

// ---------------------------------------------------------------- problem dims
constexpr int Bb   = 2;
constexpr int Tt   = 2048;
constexpr int Dd   = 1024;
constexpr int Hh   = 16;
constexpr int HDim = 64;
constexpr int BT   = Bb * Tt;      // 4096
constexpr int BHn  = Bb * Hh;      // 32
constexpr int CH   = 64;           // chunk length (attention)
constexpr int NCH  = Tt / CH;      // 32

// ---------------------------------------------------------------- scratch
__device__ float g_Q[BHn * Tt * HDim];
__device__ float g_K[BHn * Tt * HDim];
__device__ float g_V[BHn * Tt * HDim];
__device__ float g_Y[BHn * Tt * HDim];
__device__ float g_cs[BHn * NCH * HDim * HDim];
__device__ float g_sp[BHn * NCH * HDim * HDim];

extern __shared__ char dyn_smem[];

// ---------------------------------------------------------------- helpers
// pack two floats to fp16x2: low half = lo_val, high half = hi_val
__device__ __forceinline__ uint32_t packh(float lo_val, float hi_val) {
    uint32_t r;
    asm("cvt.rn.f16x2.f32 %0, %1, %2;" : "=r"(r) : "f"(hi_val), "f"(lo_val));
    return r;
}
__device__ __forceinline__ float2 unpackh(uint32_t h) {
    __half2 hh = *reinterpret_cast<__half2*>(&h);
    return __half22float2(hh);
}

__device__ __forceinline__ void mma_f16(float* c, const uint32_t* a, const uint32_t* b) {
    asm volatile(
        "mma.sync.aligned.m16n8k16.row.col.f32.f16.f16.f32 "
        "{%0,%1,%2,%3}, {%4,%5,%6,%7}, {%8,%9}, {%0,%1,%2,%3};"
        : "+f"(c[0]), "+f"(c[1]), "+f"(c[2]), "+f"(c[3])
        : "r"(a[0]), "r"(a[1]), "r"(a[2]), "r"(a[3]), "r"(b[0]), "r"(b[1]));
}

__device__ __forceinline__ void ldmx4(uint32_t* r, uint32_t saddr) {
    asm volatile("ldmatrix.sync.aligned.m8n8.x4.shared.b16 {%0,%1,%2,%3}, [%4];"
                 : "=r"(r[0]), "=r"(r[1]), "=r"(r[2]), "=r"(r[3]) : "r"(saddr));
}

// ---------------------------------------------------------------- tc_gemm cfg
constexpr int TM = 128, TN = 128, KC = 32;   // CTA tile + K chunk (floats)
constexpr int NKC = Dd / KC;                 // 32
constexpr int PAD_K = 40;                    // fp16 row stride (conflict-free)
constexpr int TILE_B = 128 * PAD_K * 2;      // 10240 bytes per fp16 tile
constexpr int OFF_AH = 0;
constexpr int OFF_B  = TILE_B;
constexpr int BUF_B  = 2 * TILE_B;           // 20480 per stage
constexpr int GEMM_SMEM = 2 * BUF_B;         // 40960 (dynamic, double buffer)

// ---------------------------------------------------------------------------
// Tensor-core GEMM via mma.sync + ldmatrix, plain fp16 operands, fp32 accum:
//   out[m,n] = sum_k A16[m,k] * W16[n,k] + bias[n]
// mode 0: z = blockIdx.z selects Wq/Wk/Wv + bias, dst = g_Q/g_K/g_V head-major
// mode 1: W = Wo (w0), bias = b0, A gathered from g_Y head-major, dst = outp
// ---------------------------------------------------------------------------
__global__ __launch_bounds__(256) void tc_gemm(const float* __restrict__ Xsrc,
                                               const float* __restrict__ w0,
                                               const float* __restrict__ w1,
                                               const float* __restrict__ w2,
                                               const float* __restrict__ b0p,
                                               const float* __restrict__ b1p,
                                               const float* __restrict__ b2p,
                                               float* __restrict__ outp,
                                               int mode)
{
    char* smem = dyn_smem;
    const int tid  = threadIdx.x;
    const int wid  = tid >> 5;
    const int lane = tid & 31;
    const int z    = blockIdx.z;
    const int bn = blockIdx.x * TN;
    const int bm = blockIdx.y * TM;
    const float* W    = (z == 0) ? w0 : (z == 1) ? w1 : w2;
    const float* bias = (z == 0) ? b0p : (z == 1) ? b1p : b2p;

    uint32_t sbase;
    asm("{ .reg .u64 t; cvta.to.shared.u64 t, %1; cvt.u32.u64 %0, t; }"
        : "=r"(sbase) : "l"((const void*)smem));

    const int m0w = (wid >> 2) * 64;      // warp row offset
    const int n0w = (wid & 3) * 32;       // warp col offset
    const int lrow  = lane >> 2;
    const int lcol2 = (lane & 3) * 2;

    // ldmatrix per-lane base offsets (bytes)
    const uint32_t a_lane = (uint32_t)(((m0w + ((lane >> 3) & 1) * 8 + (lane & 7)) * PAD_K
                                        + (lane >> 4) * 8) * 2);
    const uint32_t b_lane = (uint32_t)(((n0w + (lane >> 4) * 8 + (lane & 7)) * PAD_K
                                        + ((lane >> 3) & 1) * 8) * 2);

    float c[4][4][4];
#pragma unroll
    for (int mi = 0; mi < 4; mi++)
#pragma unroll
        for (int ni = 0; ni < 4; ni++)
#pragma unroll
            for (int r = 0; r < 4; r++) c[mi][ni][r] = 0.0f;

    float4 pa[4], pb[4];

    // loader: fetch chunk k0 into pa/pb
    auto fetch = [&](int k0) {
#pragma unroll
        for (int t = 0; t < 4; t++) {
            int u = tid + t * 256, row = u >> 3, c4 = (u & 7) * 4;
            if (mode == 0) {
                pa[t] = *(const float4*)(Xsrc + (size_t)(bm + row) * Dd + k0 + c4);
            } else {
                int m = bm + row, b = m >> 11, tt = m & 2047;
                int k = k0 + c4, h = k >> 6, hd = k & 63;
                pa[t] = *(const float4*)(g_Y + (((size_t)(b * Hh + h) * Tt) + tt) * HDim + hd);
            }
            pb[t] = *(const float4*)(W + (size_t)(bn + row) * Dd + k0 + c4);
        }
    };
    // converter: A, B -> single fp16 tiles of buffer `bo`
    auto stash = [&](int bo) {
#pragma unroll
        for (int t = 0; t < 4; t++) {
            int u = tid + t * 256, row = u >> 3, c4 = (u & 7) * 4;
            int boff = bo + (row * PAD_K + c4) * 2;
            {
                float4 v = pa[t];
                *(uint2*)(smem + OFF_AH + boff) = make_uint2(packh(v.x, v.y), packh(v.z, v.w));
            }
            {
                float4 v = pb[t];
                *(uint2*)(smem + OFF_B + boff) = make_uint2(packh(v.x, v.y), packh(v.z, v.w));
            }
        }
    };

    // prologue: chunk 0 -> buf 0; prefetch chunk 1
    fetch(0);
    stash(0);
    fetch(KC);

    for (int ck = 0; ck < NKC; ck++) {
        __syncthreads();
        const uint32_t bo = (uint32_t)((ck & 1) * BUF_B);

        // ---- MMA phase on current buffer
#pragma unroll
        for (int kk = 0; kk < KC; kk += 16) {
            uint32_t ah[4][4];
#pragma unroll
            for (int mi = 0; mi < 4; mi++) {
                uint32_t ad = sbase + bo + OFF_AH + a_lane + (uint32_t)((mi * 16 * PAD_K + kk) * 2);
                ldmx4(ah[mi], ad);
            }
            uint32_t bh[4][2];
#pragma unroll
            for (int np = 0; np < 2; np++) {
                uint32_t bd = sbase + bo + OFF_B + b_lane + (uint32_t)((np * 16 * PAD_K + kk) * 2);
                uint32_t r[4];
                ldmx4(r, bd);
                bh[np * 2][0] = r[0]; bh[np * 2][1] = r[1];
                bh[np * 2 + 1][0] = r[2]; bh[np * 2 + 1][1] = r[3];
            }
#pragma unroll
            for (int mi = 0; mi < 4; mi++)
#pragma unroll
                for (int ni = 0; ni < 4; ni++)
                    mma_f16(c[mi][ni], ah[mi], bh[ni]);
        }

        // ---- store chunk ck+1 into alternate buffer (under the MMAs)
        if (ck + 1 < NKC) stash(((ck + 1) & 1) * BUF_B);
        // ---- prefetch chunk ck+2
        if (ck + 2 < NKC) fetch((ck + 2) * KC);
    }

    // ---- epilogue
#pragma unroll
    for (int mi = 0; mi < 4; mi++) {
        int row0 = bm + m0w + mi * 16 + lrow;
        int row1 = row0 + 8;
#pragma unroll
        for (int ni = 0; ni < 4; ni++) {
            int n = bn + n0w + ni * 8 + lcol2;
            float bb0 = bias[n], bb1 = bias[n + 1];
            float2 v0 = make_float2(c[mi][ni][0] + bb0, c[mi][ni][1] + bb1);
            float2 v1 = make_float2(c[mi][ni][2] + bb0, c[mi][ni][3] + bb1);
            if (mode == 0) {
                float* base = (z == 0) ? g_Q : (z == 1) ? g_K : g_V;
                int h = n >> 6, hd = n & 63;
                int batch0 = row0 >> 11, t0 = row0 & 2047;
                int batch1 = row1 >> 11, t1 = row1 & 2047;
                *(float2*)(base + (((size_t)(batch0 * Hh + h) * Tt) + t0) * HDim + hd) = v0;
                *(float2*)(base + (((size_t)(batch1 * Hh + h) * Tt) + t1) * HDim + hd) = v1;
            } else {
                *(float2*)(outp + (size_t)row0 * Dd + n) = v0;
                *(float2*)(outp + (size_t)row1 * Dd + n) = v1;
            }
        }
    }
}

// ---------------------------------------------------------------------------
// Per-chunk state sums: M[p,n] = sum_{t in chunk} V[t,p] * K[t,n]
// 64 threads, 8x8 microtile (fp32 — feeds fp32 states).
// ---------------------------------------------------------------------------
__global__ __launch_bounds__(64) void chunk_sums()
{
    __shared__ float Ks[64 * 64];
    __shared__ float Vs[64 * 64];
    const int bh = blockIdx.y, c = blockIdx.x;
    const int tid = threadIdx.x;
    const float* Kg = g_K + ((size_t)bh * Tt + c * CH) * HDim;
    const float* Vg = g_V + ((size_t)bh * Tt + c * CH) * HDim;
    for (int i = tid; i < 1024; i += 64) {
        ((float4*)Ks)[i] = ((const float4*)Kg)[i];
        ((float4*)Vs)[i] = ((const float4*)Vg)[i];
    }
    __syncthreads();
    const int tx = tid & 7, ty = tid >> 3;
    float acc[8][8];
#pragma unroll
    for (int i = 0; i < 8; i++)
#pragma unroll
        for (int j = 0; j < 8; j++) acc[i][j] = 0.0f;
#pragma unroll 4
    for (int t = 0; t < 64; t++) {
        float rv[8], rk[8];
        *(float4*)(rv)     = *(const float4*)(Vs + t * 64 + ty * 8);
        *(float4*)(rv + 4) = *(const float4*)(Vs + t * 64 + ty * 8 + 4);
        *(float4*)(rk)     = *(const float4*)(Ks + t * 64 + tx * 8);
        *(float4*)(rk + 4) = *(const float4*)(Ks + t * 64 + tx * 8 + 4);
#pragma unroll
        for (int i = 0; i < 8; i++)
#pragma unroll
            for (int j = 0; j < 8; j++) acc[i][j] += rv[i] * rk[j];
    }
    float* dst = g_cs + ((size_t)bh * NCH + c) * 4096;
#pragma unroll
    for (int i = 0; i < 8; i++)
#pragma unroll
        for (int j = 0; j < 8; j += 4)
            *(float4*)(dst + (ty * 8 + i) * 64 + tx * 8 + j) =
                make_float4(acc[i][j], acc[i][j + 1], acc[i][j + 2], acc[i][j + 3]);
}

// ---------------------------------------------------------------------------
// Exclusive prefix over chunks (parallelized: 512 blocks)
// ---------------------------------------------------------------------------
__global__ __launch_bounds__(256) void prefix_kernel()
{
    const int bh = blockIdx.x;
    const int e = blockIdx.y * 256 + threadIdx.x;
    float acc = 0.0f;
#pragma unroll
    for (int c = 0; c < NCH; c++) {
        size_t off = ((size_t)bh * NCH + c) * 4096 + e;
        g_sp[off] = acc;
        acc += g_cs[off];
    }
}

// ---------------------------------------------------------------------------
// Tensor-core intra-chunk attention, FULL 2-term split on ALL operands
// (3-term MMA products -> fp32-grade accuracy here):
//   scores A[t][s] = mask(Q[t]·K[s]);  Y[t][p] = A·V + Q·Sp^T
// smem fp16 tiles [64][TPAD]: Qh Ql Kh Kl Vth Vtl Sph Spl;
// Am hi/lo alias Kh/Kl after phase 1.
// ---------------------------------------------------------------------------
constexpr int TPAD = 72;                     // 144B stride -> conflict-free ldmatrix
constexpr int T_TILE2 = 64 * TPAD * 2;       // 9216 B
constexpr int OFF_QH2  = 0;
constexpr int OFF_QL2  = 1 * T_TILE2;
constexpr int OFF_KH2  = 2 * T_TILE2;
constexpr int OFF_KL2  = 3 * T_TILE2;
constexpr int OFF_VTH2 = 4 * T_TILE2;
constexpr int OFF_VTL2 = 5 * T_TILE2;
constexpr int OFF_SPH2 = 6 * T_TILE2;
constexpr int OFF_SPL2 = 7 * T_TILE2;
constexpr int OFF_AH2  = OFF_KH2;            // aliases
constexpr int OFF_AL2  = OFF_KL2;
constexpr int ATTN_SMEM = 8 * T_TILE2;       // 73728 B

__global__ __launch_bounds__(256) void attn_tc()
{
    char* smem = dyn_smem;
    uint32_t sbase;
    asm("{ .reg .u64 t; cvta.to.shared.u64 t, %1; cvt.u32.u64 %0, t; }"
        : "=r"(sbase) : "l"((const void*)smem));
    const int bh = blockIdx.y, c = blockIdx.x;
    const int tid = threadIdx.x;
    const int wid = tid >> 5;
    const int lane = tid & 31;
    const float* Qg = g_Q + ((size_t)bh * Tt + c * CH) * HDim;
    const float* Kg = g_K + ((size_t)bh * Tt + c * CH) * HDim;
    const float* Vg = g_V + ((size_t)bh * Tt + c * CH) * HDim;
    const float* Sg = g_sp + ((size_t)bh * NCH + c) * 4096;

    __half* sQh  = (__half*)(smem + OFF_QH2);
    __half* sQl  = (__half*)(smem + OFF_QL2);
    __half* sKh  = (__half*)(smem + OFF_KH2);
    __half* sKl  = (__half*)(smem + OFF_KL2);
    __half* sVth = (__half*)(smem + OFF_VTH2);
    __half* sVtl = (__half*)(smem + OFF_VTL2);
    __half* sSph = (__half*)(smem + OFF_SPH2);
    __half* sSpl = (__half*)(smem + OFF_SPL2);
    __half* sAh  = (__half*)(smem + OFF_AH2);
    __half* sAl  = (__half*)(smem + OFF_AL2);

    // ---- load + convert (hi/lo split for every operand)
    for (int i = tid; i < 1024; i += 256) {
        int r = i >> 4;               // row 0..63
        int c4 = (i & 15) << 2;       // col base
        float4 q = *(const float4*)(Qg + r * 64 + c4);
        float4 k = *(const float4*)(Kg + r * 64 + c4);
        float4 v = *(const float4*)(Vg + r * 64 + c4);
        float4 s = *(const float4*)(Sg + r * 64 + c4);
        {   // Q hi/lo
            uint32_t h01 = packh(q.x, q.y), h23 = packh(q.z, q.w);
            float2 f01 = unpackh(h01), f23 = unpackh(h23);
            *(uint2*)(sQh + r * TPAD + c4) = make_uint2(h01, h23);
            *(uint2*)(sQl + r * TPAD + c4) =
                make_uint2(packh(q.x - f01.x, q.y - f01.y), packh(q.z - f23.x, q.w - f23.y));
        }
        {   // K hi/lo
            uint32_t h01 = packh(k.x, k.y), h23 = packh(k.z, k.w);
            float2 f01 = unpackh(h01), f23 = unpackh(h23);
            *(uint2*)(sKh + r * TPAD + c4) = make_uint2(h01, h23);
            *(uint2*)(sKl + r * TPAD + c4) =
                make_uint2(packh(k.x - f01.x, k.y - f01.y), packh(k.z - f23.x, k.w - f23.y));
        }
        {   // Sp hi/lo  (gmem already [p][n])
            uint32_t h01 = packh(s.x, s.y), h23 = packh(s.z, s.w);
            float2 f01 = unpackh(h01), f23 = unpackh(h23);
            *(uint2*)(sSph + r * TPAD + c4) = make_uint2(h01, h23);
            *(uint2*)(sSpl + r * TPAD + c4) =
                make_uint2(packh(s.x - f01.x, s.y - f01.y), packh(s.z - f23.x, s.w - f23.y));
        }
        {   // V transposed hi/lo: sVt*[p][s], p = c4+j, s = r
            float vv[4] = {v.x, v.y, v.z, v.w};
#pragma unroll
            for (int j = 0; j < 4; j++) {
                __half h = __float2half(vv[j]);
                sVth[(c4 + j) * TPAD + r] = h;
                sVtl[(c4 + j) * TPAD + r] = __float2half(vv[j] - __half2float(h));
            }
        }
    }
    __syncthreads();

    const int mw = (wid >> 1) * 16;       // warp M (t) base
    const int nw = (wid & 1) * 32;        // warp N (s / p) base
    const int lrow  = lane >> 2;
    const int lcol2 = (lane & 3) * 2;

    const uint32_t a_lane = (uint32_t)(((mw + ((lane >> 3) & 1) * 8 + (lane & 7)) * TPAD
                                        + (lane >> 4) * 8) * 2);
    const uint32_t b_lane = (uint32_t)(((nw + (lane >> 4) * 8 + (lane & 7)) * TPAD
                                        + ((lane >> 3) & 1) * 8) * 2);

    // ---- phase 1: scores (3-term): Qh·Kh + Qh·Kl + Ql·Kh
    float a[4][4];
#pragma unroll
    for (int ni = 0; ni < 4; ni++)
#pragma unroll
        for (int r = 0; r < 4; r++) a[ni][r] = 0.0f;
#pragma unroll
    for (int kk = 0; kk < 64; kk += 16) {
        uint32_t qh[4], ql[4];
        uint32_t ad = sbase + OFF_QH2 + a_lane + (uint32_t)(kk * 2);
        ldmx4(qh, ad);
        ldmx4(ql, ad + (OFF_QL2 - OFF_QH2));
        uint32_t bkh[4][2], bkl[4][2];
#pragma unroll
        for (int np = 0; np < 2; np++) {
            uint32_t bd = sbase + OFF_KH2 + b_lane + (uint32_t)((np * 16 * TPAD + kk) * 2);
            uint32_t r4[4];
            ldmx4(r4, bd);
            bkh[np * 2][0] = r4[0]; bkh[np * 2][1] = r4[1];
            bkh[np * 2 + 1][0] = r4[2]; bkh[np * 2 + 1][1] = r4[3];
            ldmx4(r4, bd + (OFF_KL2 - OFF_KH2));
            bkl[np * 2][0] = r4[0]; bkl[np * 2][1] = r4[1];
            bkl[np * 2 + 1][0] = r4[2]; bkl[np * 2 + 1][1] = r4[3];
        }
#pragma unroll
        for (int ni = 0; ni < 4; ni++) {
            mma_f16(a[ni], qh, bkh[ni]);
            mma_f16(a[ni], qh, bkl[ni]);
            mma_f16(a[ni], ql, bkh[ni]);
        }
    }
    __syncthreads();   // all K reads done before Am aliases overwrite

    // ---- write masked scores (hi/lo split) into the aliased K tiles
#pragma unroll
    for (int ni = 0; ni < 4; ni++)
#pragma unroll
        for (int r = 0; r < 4; r++) {
            int t = mw + lrow + (r >> 1) * 8;
            int s = nw + ni * 8 + lcol2 + (r & 1);
            float v = (s <= t) ? a[ni][r] : 0.0f;
            __half h = __float2half(v);
            sAh[t * TPAD + s] = h;
            sAl[t * TPAD + s] = __float2half(v - __half2float(h));
        }

    // ---- phase 2b (independent of Am): y += Q·Sp^T (3-term)
    float y[4][4];
#pragma unroll
    for (int ni = 0; ni < 4; ni++)
#pragma unroll
        for (int r = 0; r < 4; r++) y[ni][r] = 0.0f;
#pragma unroll
    for (int kk = 0; kk < 64; kk += 16) {
        uint32_t qh[4], ql[4];
        uint32_t ad = sbase + OFF_QH2 + a_lane + (uint32_t)(kk * 2);
        ldmx4(qh, ad);
        ldmx4(ql, ad + (OFF_QL2 - OFF_QH2));
        uint32_t bsh[4][2], bsl[4][2];
#pragma unroll
        for (int np = 0; np < 2; np++) {
            uint32_t bd = sbase + OFF_SPH2 + b_lane + (uint32_t)((np * 16 * TPAD + kk) * 2);
            uint32_t r4[4];
            ldmx4(r4, bd);
            bsh[np * 2][0] = r4[0]; bsh[np * 2][1] = r4[1];
            bsh[np * 2 + 1][0] = r4[2]; bsh[np * 2 + 1][1] = r4[3];
            ldmx4(r4, bd + (OFF_SPL2 - OFF_SPH2));
            bsl[np * 2][0] = r4[0]; bsl[np * 2][1] = r4[1];
            bsl[np * 2 + 1][0] = r4[2]; bsl[np * 2 + 1][1] = r4[3];
        }
#pragma unroll
        for (int ni = 0; ni < 4; ni++) {
            mma_f16(y[ni], qh, bsh[ni]);
            mma_f16(y[ni], qh, bsl[ni]);
            mma_f16(y[ni], ql, bsh[ni]);
        }
    }

    __syncthreads();   // Am published by all warps

    // ---- phase 2a: y += Am·V (3-term; B = Vt[p][s])
#pragma unroll
    for (int kk = 0; kk < 64; kk += 16) {
        uint32_t amh[4], aml[4];
        uint32_t ad = sbase + OFF_AH2 + a_lane + (uint32_t)(kk * 2);
        ldmx4(amh, ad);
        ldmx4(aml, ad + (OFF_AL2 - OFF_AH2));
        uint32_t bvh[4][2], bvl[4][2];
#pragma unroll
        for (int np = 0; np < 2; np++) {
            uint32_t bd = sbase + OFF_VTH2 + b_lane + (uint32_t)((np * 16 * TPAD + kk) * 2);
            uint32_t r4[4];
            ldmx4(r4, bd);
            bvh[np * 2][0] = r4[0]; bvh[np * 2][1] = r4[1];
            bvh[np * 2 + 1][0] = r4[2]; bvh[np * 2 + 1][1] = r4[3];
            ldmx4(r4, bd + (OFF_VTL2 - OFF_VTH2));
            bvl[np * 2][0] = r4[0]; bvl[np * 2][1] = r4[1];
            bvl[np * 2 + 1][0] = r4[2]; bvl[np * 2 + 1][1] = r4[3];
        }
#pragma unroll
        for (int ni = 0; ni < 4; ni++) {
            mma_f16(y[ni], amh, bvh[ni]);
            mma_f16(y[ni], amh, bvl[ni]);
            mma_f16(y[ni], aml, bvh[ni]);
        }
    }

    // ---- epilogue: Y[t][p] fp32
    float* Yg = g_Y + ((size_t)bh * Tt + c * CH) * HDim;
#pragma unroll
    for (int ni = 0; ni < 4; ni++) {
        int p = nw + ni * 8 + lcol2;
        int t0 = mw + lrow, t1 = t0 + 8;
        *(float2*)(Yg + t0 * 64 + p) = make_float2(y[ni][0], y[ni][1]);
        *(float2*)(Yg + t1 * 64 + p) = make_float2(y[ni][2], y[ni][3]);
    }
}

// ---------------------------------------------------------------------------
extern "C" void kernel_launch(void* const* d_in, const int* in_sizes, int n_in,
                              void* d_out, int out_size)
{
    const float* x  = (const float*)d_in[0];
    const float* Wq = (const float*)d_in[1];
    const float* bq = (const float*)d_in[2];
    const float* Wk = (const float*)d_in[3];
    const float* bk = (const float*)d_in[4];
    const float* Wv = (const float*)d_in[5];
    const float* bv = (const float*)d_in[6];
    const float* Wo = (const float*)d_in[7];
    const float* bo = (const float*)d_in[8];
    float* out = (float*)d_out;

    cudaFuncSetAttribute(tc_gemm, cudaFuncAttributeMaxDynamicSharedMemorySize, GEMM_SMEM);
    cudaFuncSetAttribute(attn_tc, cudaFuncAttributeMaxDynamicSharedMemorySize, ATTN_SMEM);

    // fused Q/K/V projections (z selects weight/bias/dst)
    tc_gemm<<<dim3(Dd / TN, BT / TM, 3), 256, GEMM_SMEM>>>(x, Wq, Wk, Wv, bq, bk, bv, nullptr, 0);
    chunk_sums<<<dim3(NCH, BHn), 64>>>();
    prefix_kernel<<<dim3(BHn, 16), 256>>>();
    attn_tc<<<dim3(NCH, BHn), 256, ATTN_SMEM>>>();
    tc_gemm<<<dim3(Dd / TN, BT / TM, 1), 256, GEMM_SMEM>>>(nullptr, Wo, nullptr, nullptr, bo, nullptr, nullptr, out, 1);
}

// round 14
// speedup vs baseline: 3.0319x; 1.0021x over previous
#include <cuda_runtime.h>
#include <cuda_fp16.h>
#include <cstdint>

// ---------------------------------------------------------------- problem dims
constexpr int Bb   = 2;
constexpr int Tt   = 2048;
constexpr int Dd   = 1024;
constexpr int Hh   = 16;
constexpr int HDim = 64;
constexpr int BT   = Bb * Tt;      // 4096
constexpr int BHn  = Bb * Hh;      // 32
constexpr int CH   = 64;           // chunk length (attention)
constexpr int NCH  = Tt / CH;      // 32

// ---------------------------------------------------------------- scratch
__device__ float  g_Q[BHn * Tt * HDim];
__device__ float  g_K[BHn * Tt * HDim];
__device__ float  g_V[BHn * Tt * HDim];
__device__ float  g_cs[BHn * NCH * HDim * HDim];
__device__ float  g_sp[BHn * NCH * HDim * HDim];
__device__ __half g_X16[BT * Dd];          // fp16 input activations
__device__ __half g_W16[4 * Dd * Dd];      // fp16 weights (q,k,v,o)
__device__ __half g_Y16[BT * Dd];          // fp16 attention output, row-major

extern __shared__ char dyn_smem[];

// ---------------------------------------------------------------- helpers
// pack two floats to fp16x2: low half = lo_val, high half = hi_val
__device__ __forceinline__ uint32_t packh(float lo_val, float hi_val) {
    uint32_t r;
    asm("cvt.rn.f16x2.f32 %0, %1, %2;" : "=r"(r) : "f"(hi_val), "f"(lo_val));
    return r;
}
__device__ __forceinline__ float2 unpackh(uint32_t h) {
    __half2 hh = *reinterpret_cast<__half2*>(&h);
    return __half22float2(hh);
}

__device__ __forceinline__ void mma_f16(float* c, const uint32_t* a, const uint32_t* b) {
    asm volatile(
        "mma.sync.aligned.m16n8k16.row.col.f32.f16.f16.f32 "
        "{%0,%1,%2,%3}, {%4,%5,%6,%7}, {%8,%9}, {%0,%1,%2,%3};"
        : "+f"(c[0]), "+f"(c[1]), "+f"(c[2]), "+f"(c[3])
        : "r"(a[0]), "r"(a[1]), "r"(a[2]), "r"(a[3]), "r"(b[0]), "r"(b[1]));
}

__device__ __forceinline__ void ldmx4(uint32_t* r, uint32_t saddr) {
    asm volatile("ldmatrix.sync.aligned.m8n8.x4.shared.b16 {%0,%1,%2,%3}, [%4];"
                 : "=r"(r[0]), "=r"(r[1]), "=r"(r[2]), "=r"(r[3]) : "r"(saddr));
}

// ---------------------------------------------------------------- converters
__global__ __launch_bounds__(256) void convert_x(const float4* __restrict__ src)
{
    int i = blockIdx.x * 256 + threadIdx.x;          // over BT*Dd/4
    float4 v = src[i];
    ((uint2*)g_X16)[i] = make_uint2(packh(v.x, v.y), packh(v.z, v.w));
}
__global__ __launch_bounds__(256) void convert_w(const float4* __restrict__ w0,
                                                 const float4* __restrict__ w1,
                                                 const float4* __restrict__ w2,
                                                 const float4* __restrict__ w3)
{
    int z = blockIdx.y;
    const float4* src = (z == 0) ? w0 : (z == 1) ? w1 : (z == 2) ? w2 : w3;
    int i = blockIdx.x * 256 + threadIdx.x;          // over Dd*Dd/4
    float4 v = src[i];
    ((uint2*)g_W16)[(size_t)z * (Dd * Dd / 4) + i] = make_uint2(packh(v.x, v.y), packh(v.z, v.w));
}

// ---------------------------------------------------------------- tc_gemm cfg
constexpr int TM = 128, TN = 128, KC = 32;   // CTA tile + K chunk
constexpr int NKC = Dd / KC;                 // 32
constexpr int PAD_K = 40;                    // fp16 row stride (conflict-free)
constexpr int TILE_B = 128 * PAD_K * 2;      // 10240 bytes per fp16 tile
constexpr int OFF_A = 0;
constexpr int OFF_B = TILE_B;
constexpr int BUF_B = 2 * TILE_B;            // 20480 per stage
constexpr int GEMM_SMEM = 2 * BUF_B;         // 40960 (dynamic, double buffer)

// ---------------------------------------------------------------------------
// Tensor-core GEMM, PRE-CONVERTED fp16 operands (mainloop = copies + MMAs):
//   out[m,n] = sum_k A16[m,k] * W16[widx][n,k] + bias[n]
// mode 0: A = g_X16, widx = z, dst = g_Q/g_K/g_V head-major fp32
// mode 1: A = g_Y16, widx = 3, dst = outp row-major fp32
// ---------------------------------------------------------------------------
__global__ __launch_bounds__(256) void tc_gemm(const float* __restrict__ b0p,
                                               const float* __restrict__ b1p,
                                               const float* __restrict__ b2p,
                                               float* __restrict__ outp,
                                               int mode)
{
    char* smem = dyn_smem;
    const int tid  = threadIdx.x;
    const int wid  = tid >> 5;
    const int lane = tid & 31;
    const int z    = blockIdx.z;
    const int bn = blockIdx.x * TN;
    const int bm = blockIdx.y * TM;
    const int widx = (mode == 0) ? z : 3;
    const float* bias = (z == 0) ? b0p : (z == 1) ? b1p : b2p;
    const __half* A16 = (mode == 0) ? g_X16 : g_Y16;
    const __half* W16 = g_W16 + (size_t)widx * Dd * Dd;

    uint32_t sbase;
    asm("{ .reg .u64 t; cvta.to.shared.u64 t, %1; cvt.u32.u64 %0, t; }"
        : "=r"(sbase) : "l"((const void*)smem));

    const int m0w = (wid >> 2) * 64;      // warp row offset
    const int n0w = (wid & 3) * 32;       // warp col offset
    const int lrow  = lane >> 2;
    const int lcol2 = (lane & 3) * 2;

    const uint32_t a_lane = (uint32_t)(((m0w + ((lane >> 3) & 1) * 8 + (lane & 7)) * PAD_K
                                        + (lane >> 4) * 8) * 2);
    const uint32_t b_lane = (uint32_t)(((n0w + (lane >> 4) * 8 + (lane & 7)) * PAD_K
                                        + ((lane >> 3) & 1) * 8) * 2);

    float c[4][4][4];
#pragma unroll
    for (int mi = 0; mi < 4; mi++)
#pragma unroll
        for (int ni = 0; ni < 4; ni++)
#pragma unroll
            for (int r = 0; r < 4; r++) c[mi][ni][r] = 0.0f;

    // per-thread copy slots: u = tid + t*256, row = u>>2 (0..127), cg = (u&3)*8 halfs
    const int row_ld = tid >> 2;
    const int cg     = (tid & 3) * 8;
    uint4 pa[2], pb[2];

    auto fetch = [&](int k0) {
#pragma unroll
        for (int t = 0; t < 2; t++) {
            int row = row_ld + t * 64;
            pa[t] = *(const uint4*)(A16 + (size_t)(bm + row) * Dd + k0 + cg);
            pb[t] = *(const uint4*)(W16 + (size_t)(bn + row) * Dd + k0 + cg);
        }
    };
    auto stash = [&](int bo) {
#pragma unroll
        for (int t = 0; t < 2; t++) {
            int row = row_ld + t * 64;
            int boff = bo + (row * PAD_K + cg) * 2;
            *(uint4*)(smem + OFF_A + boff) = pa[t];
            *(uint4*)(smem + OFF_B + boff) = pb[t];
        }
    };

    fetch(0);
    stash(0);
    fetch(KC);

    for (int ck = 0; ck < NKC; ck++) {
        __syncthreads();
        const uint32_t bo = (uint32_t)((ck & 1) * BUF_B);

#pragma unroll
        for (int kk = 0; kk < KC; kk += 16) {
            uint32_t ah[4][4];
#pragma unroll
            for (int mi = 0; mi < 4; mi++)
                ldmx4(ah[mi], sbase + bo + OFF_A + a_lane + (uint32_t)((mi * 16 * PAD_K + kk) * 2));
            uint32_t bh[4][2];
#pragma unroll
            for (int np = 0; np < 2; np++) {
                uint32_t r[4];
                ldmx4(r, sbase + bo + OFF_B + b_lane + (uint32_t)((np * 16 * PAD_K + kk) * 2));
                bh[np * 2][0] = r[0]; bh[np * 2][1] = r[1];
                bh[np * 2 + 1][0] = r[2]; bh[np * 2 + 1][1] = r[3];
            }
#pragma unroll
            for (int mi = 0; mi < 4; mi++)
#pragma unroll
                for (int ni = 0; ni < 4; ni++)
                    mma_f16(c[mi][ni], ah[mi], bh[ni]);
        }

        if (ck + 1 < NKC) stash(((ck + 1) & 1) * BUF_B);
        if (ck + 2 < NKC) fetch((ck + 2) * KC);
    }

    // ---- epilogue
#pragma unroll
    for (int mi = 0; mi < 4; mi++) {
        int row0 = bm + m0w + mi * 16 + lrow;
        int row1 = row0 + 8;
#pragma unroll
        for (int ni = 0; ni < 4; ni++) {
            int n = bn + n0w + ni * 8 + lcol2;
            float bb0 = bias[n], bb1 = bias[n + 1];
            float2 v0 = make_float2(c[mi][ni][0] + bb0, c[mi][ni][1] + bb1);
            float2 v1 = make_float2(c[mi][ni][2] + bb0, c[mi][ni][3] + bb1);
            if (mode == 0) {
                float* base = (z == 0) ? g_Q : (z == 1) ? g_K : g_V;
                int h = n >> 6, hd = n & 63;
                int batch0 = row0 >> 11, t0 = row0 & 2047;
                int batch1 = row1 >> 11, t1 = row1 & 2047;
                *(float2*)(base + (((size_t)(batch0 * Hh + h) * Tt) + t0) * HDim + hd) = v0;
                *(float2*)(base + (((size_t)(batch1 * Hh + h) * Tt) + t1) * HDim + hd) = v1;
            } else {
                *(float2*)(outp + (size_t)row0 * Dd + n) = v0;
                *(float2*)(outp + (size_t)row1 * Dd + n) = v1;
            }
        }
    }
}

// ---------------------------------------------------------------- attn cfg
constexpr int TPAD = 72;                     // 144B stride -> conflict-free ldmatrix
constexpr int T_TILE2 = 64 * TPAD * 2;       // 9216 B

// ---------------------------------------------------------------------------
// Tensor-core chunk sums: cs[p][n] = sum_t V[t][p] * K[t][n]
// 2-term split both operands (3-term MMA): fp32-grade.
// smem: Vt hi/lo [p][t], Kt hi/lo [n][t]. Warp grid 4x2 (mw 16 p-rows, nw 32 n).
// ---------------------------------------------------------------------------
constexpr int OFF_CVH = 0;
constexpr int OFF_CVL = 1 * T_TILE2;
constexpr int OFF_CKH = 2 * T_TILE2;
constexpr int OFF_CKL = 3 * T_TILE2;
constexpr int CS_SMEM = 4 * T_TILE2;         // 36864 B

__global__ __launch_bounds__(256) void chunk_sums_tc()
{
    char* smem = dyn_smem;
    uint32_t sbase;
    asm("{ .reg .u64 t; cvta.to.shared.u64 t, %1; cvt.u32.u64 %0, t; }"
        : "=r"(sbase) : "l"((const void*)smem));
    const int bh = blockIdx.y, c = blockIdx.x;
    const int tid = threadIdx.x;
    const int wid = tid >> 5;
    const int lane = tid & 31;
    const float* Kg = g_K + ((size_t)bh * Tt + c * CH) * HDim;
    const float* Vg = g_V + ((size_t)bh * Tt + c * CH) * HDim;

    __half* sVh = (__half*)(smem + OFF_CVH);
    __half* sVl = (__half*)(smem + OFF_CVL);
    __half* sKh = (__half*)(smem + OFF_CKH);
    __half* sKl = (__half*)(smem + OFF_CKL);

    for (int i = tid; i < 1024; i += 256) {
        int r = i >> 4;               // t 0..63
        int c4 = (i & 15) << 2;       // col base (p / n)
        float4 v = *(const float4*)(Vg + r * 64 + c4);
        float4 k = *(const float4*)(Kg + r * 64 + c4);
        float vv[4] = {v.x, v.y, v.z, v.w};
        float kv[4] = {k.x, k.y, k.z, k.w};
#pragma unroll
        for (int j = 0; j < 4; j++) {
            __half hv = __float2half(vv[j]);
            sVh[(c4 + j) * TPAD + r] = hv;
            sVl[(c4 + j) * TPAD + r] = __float2half(vv[j] - __half2float(hv));
            __half hk = __float2half(kv[j]);
            sKh[(c4 + j) * TPAD + r] = hk;
            sKl[(c4 + j) * TPAD + r] = __float2half(kv[j] - __half2float(hk));
        }
    }
    __syncthreads();

    const int mw = (wid >> 1) * 16;       // p base
    const int nw = (wid & 1) * 32;        // n base
    const int lrow  = lane >> 2;
    const int lcol2 = (lane & 3) * 2;

    const uint32_t a_lane = (uint32_t)(((mw + ((lane >> 3) & 1) * 8 + (lane & 7)) * TPAD
                                        + (lane >> 4) * 8) * 2);
    const uint32_t b_lane = (uint32_t)(((nw + (lane >> 4) * 8 + (lane & 7)) * TPAD
                                        + ((lane >> 3) & 1) * 8) * 2);

    float acc[4][4];
#pragma unroll
    for (int ni = 0; ni < 4; ni++)
#pragma unroll
        for (int r = 0; r < 4; r++) acc[ni][r] = 0.0f;
#pragma unroll
    for (int kk = 0; kk < 64; kk += 16) {
        uint32_t vh[4], vl[4];
        uint32_t ad = sbase + OFF_CVH + a_lane + (uint32_t)(kk * 2);
        ldmx4(vh, ad);
        ldmx4(vl, ad + (OFF_CVL - OFF_CVH));
        uint32_t kh[4][2], kl[4][2];
#pragma unroll
        for (int np = 0; np < 2; np++) {
            uint32_t bd = sbase + OFF_CKH + b_lane + (uint32_t)((np * 16 * TPAD + kk) * 2);
            uint32_t r4[4];
            ldmx4(r4, bd);
            kh[np * 2][0] = r4[0]; kh[np * 2][1] = r4[1];
            kh[np * 2 + 1][0] = r4[2]; kh[np * 2 + 1][1] = r4[3];
            ldmx4(r4, bd + (OFF_CKL - OFF_CKH));
            kl[np * 2][0] = r4[0]; kl[np * 2][1] = r4[1];
            kl[np * 2 + 1][0] = r4[2]; kl[np * 2 + 1][1] = r4[3];
        }
#pragma unroll
        for (int ni = 0; ni < 4; ni++) {
            mma_f16(acc[ni], vh, kh[ni]);
            mma_f16(acc[ni], vh, kl[ni]);
            mma_f16(acc[ni], vl, kh[ni]);
        }
    }

    float* dst = g_cs + ((size_t)bh * NCH + c) * 4096;
#pragma unroll
    for (int ni = 0; ni < 4; ni++) {
        int n = nw + ni * 8 + lcol2;
        int p0 = mw + lrow, p1 = p0 + 8;
        *(float2*)(dst + p0 * 64 + n) = make_float2(acc[ni][0], acc[ni][1]);
        *(float2*)(dst + p1 * 64 + n) = make_float2(acc[ni][2], acc[ni][3]);
    }
}

// ---------------------------------------------------------------------------
// Exclusive prefix over chunks (parallelized: 512 blocks)
// ---------------------------------------------------------------------------
__global__ __launch_bounds__(256) void prefix_kernel()
{
    const int bh = blockIdx.x;
    const int e = blockIdx.y * 256 + threadIdx.x;
    float acc = 0.0f;
#pragma unroll
    for (int c = 0; c < NCH; c++) {
        size_t off = ((size_t)bh * NCH + c) * 4096 + e;
        g_sp[off] = acc;
        acc += g_cs[off];
    }
}

// ---------------------------------------------------------------------------
// Tensor-core intra-chunk attention, FULL 2-term split on ALL operands:
//   scores A[t][s] = mask(Q[t]·K[s]);  Y[t][p] = A·V + Q·Sp^T
// Output written fp16 row-major to g_Y16 (ready for out-projection GEMM).
// ---------------------------------------------------------------------------
constexpr int OFF_QH2  = 0;
constexpr int OFF_QL2  = 1 * T_TILE2;
constexpr int OFF_KH2  = 2 * T_TILE2;
constexpr int OFF_KL2  = 3 * T_TILE2;
constexpr int OFF_VTH2 = 4 * T_TILE2;
constexpr int OFF_VTL2 = 5 * T_TILE2;
constexpr int OFF_SPH2 = 6 * T_TILE2;
constexpr int OFF_SPL2 = 7 * T_TILE2;
constexpr int OFF_AH2  = OFF_KH2;            // aliases
constexpr int OFF_AL2  = OFF_KL2;
constexpr int ATTN_SMEM = 8 * T_TILE2;       // 73728 B

__global__ __launch_bounds__(256) void attn_tc()
{
    char* smem = dyn_smem;
    uint32_t sbase;
    asm("{ .reg .u64 t; cvta.to.shared.u64 t, %1; cvt.u32.u64 %0, t; }"
        : "=r"(sbase) : "l"((const void*)smem));
    const int bh = blockIdx.y, c = blockIdx.x;
    const int tid = threadIdx.x;
    const int wid = tid >> 5;
    const int lane = tid & 31;
    const float* Qg = g_Q + ((size_t)bh * Tt + c * CH) * HDim;
    const float* Kg = g_K + ((size_t)bh * Tt + c * CH) * HDim;
    const float* Vg = g_V + ((size_t)bh * Tt + c * CH) * HDim;
    const float* Sg = g_sp + ((size_t)bh * NCH + c) * 4096;

    __half* sQh  = (__half*)(smem + OFF_QH2);
    __half* sQl  = (__half*)(smem + OFF_QL2);
    __half* sKh  = (__half*)(smem + OFF_KH2);
    __half* sKl  = (__half*)(smem + OFF_KL2);
    __half* sVth = (__half*)(smem + OFF_VTH2);
    __half* sVtl = (__half*)(smem + OFF_VTL2);
    __half* sSph = (__half*)(smem + OFF_SPH2);
    __half* sSpl = (__half*)(smem + OFF_SPL2);
    __half* sAh  = (__half*)(smem + OFF_AH2);
    __half* sAl  = (__half*)(smem + OFF_AL2);

    // ---- load + convert (hi/lo split for every operand)
    for (int i = tid; i < 1024; i += 256) {
        int r = i >> 4;
        int c4 = (i & 15) << 2;
        float4 q = *(const float4*)(Qg + r * 64 + c4);
        float4 k = *(const float4*)(Kg + r * 64 + c4);
        float4 v = *(const float4*)(Vg + r * 64 + c4);
        float4 s = *(const float4*)(Sg + r * 64 + c4);
        {
            uint32_t h01 = packh(q.x, q.y), h23 = packh(q.z, q.w);
            float2 f01 = unpackh(h01), f23 = unpackh(h23);
            *(uint2*)(sQh + r * TPAD + c4) = make_uint2(h01, h23);
            *(uint2*)(sQl + r * TPAD + c4) =
                make_uint2(packh(q.x - f01.x, q.y - f01.y), packh(q.z - f23.x, q.w - f23.y));
        }
        {
            uint32_t h01 = packh(k.x, k.y), h23 = packh(k.z, k.w);
            float2 f01 = unpackh(h01), f23 = unpackh(h23);
            *(uint2*)(sKh + r * TPAD + c4) = make_uint2(h01, h23);
            *(uint2*)(sKl + r * TPAD + c4) =
                make_uint2(packh(k.x - f01.x, k.y - f01.y), packh(k.z - f23.x, k.w - f23.y));
        }
        {
            uint32_t h01 = packh(s.x, s.y), h23 = packh(s.z, s.w);
            float2 f01 = unpackh(h01), f23 = unpackh(h23);
            *(uint2*)(sSph + r * TPAD + c4) = make_uint2(h01, h23);
            *(uint2*)(sSpl + r * TPAD + c4) =
                make_uint2(packh(s.x - f01.x, s.y - f01.y), packh(s.z - f23.x, s.w - f23.y));
        }
        {
            float vv[4] = {v.x, v.y, v.z, v.w};
#pragma unroll
            for (int j = 0; j < 4; j++) {
                __half h = __float2half(vv[j]);
                sVth[(c4 + j) * TPAD + r] = h;
                sVtl[(c4 + j) * TPAD + r] = __float2half(vv[j] - __half2float(h));
            }
        }
    }
    __syncthreads();

    const int mw = (wid >> 1) * 16;
    const int nw = (wid & 1) * 32;
    const int lrow  = lane >> 2;
    const int lcol2 = (lane & 3) * 2;

    const uint32_t a_lane = (uint32_t)(((mw + ((lane >> 3) & 1) * 8 + (lane & 7)) * TPAD
                                        + (lane >> 4) * 8) * 2);
    const uint32_t b_lane = (uint32_t)(((nw + (lane >> 4) * 8 + (lane & 7)) * TPAD
                                        + ((lane >> 3) & 1) * 8) * 2);

    // ---- phase 1: scores (3-term)
    float a[4][4];
#pragma unroll
    for (int ni = 0; ni < 4; ni++)
#pragma unroll
        for (int r = 0; r < 4; r++) a[ni][r] = 0.0f;
#pragma unroll
    for (int kk = 0; kk < 64; kk += 16) {
        uint32_t qh[4], ql[4];
        uint32_t ad = sbase + OFF_QH2 + a_lane + (uint32_t)(kk * 2);
        ldmx4(qh, ad);
        ldmx4(ql, ad + (OFF_QL2 - OFF_QH2));
        uint32_t bkh[4][2], bkl[4][2];
#pragma unroll
        for (int np = 0; np < 2; np++) {
            uint32_t bd = sbase + OFF_KH2 + b_lane + (uint32_t)((np * 16 * TPAD + kk) * 2);
            uint32_t r4[4];
            ldmx4(r4, bd);
            bkh[np * 2][0] = r4[0]; bkh[np * 2][1] = r4[1];
            bkh[np * 2 + 1][0] = r4[2]; bkh[np * 2 + 1][1] = r4[3];
            ldmx4(r4, bd + (OFF_KL2 - OFF_KH2));
            bkl[np * 2][0] = r4[0]; bkl[np * 2][1] = r4[1];
            bkl[np * 2 + 1][0] = r4[2]; bkl[np * 2 + 1][1] = r4[3];
        }
#pragma unroll
        for (int ni = 0; ni < 4; ni++) {
            mma_f16(a[ni], qh, bkh[ni]);
            mma_f16(a[ni], qh, bkl[ni]);
            mma_f16(a[ni], ql, bkh[ni]);
        }
    }
    __syncthreads();   // K reads done before Am aliases overwrite

#pragma unroll
    for (int ni = 0; ni < 4; ni++)
#pragma unroll
        for (int r = 0; r < 4; r++) {
            int t = mw + lrow + (r >> 1) * 8;
            int s = nw + ni * 8 + lcol2 + (r & 1);
            float v = (s <= t) ? a[ni][r] : 0.0f;
            __half h = __float2half(v);
            sAh[t * TPAD + s] = h;
            sAl[t * TPAD + s] = __float2half(v - __half2float(h));
        }

    // ---- phase 2b: y += Q·Sp^T (3-term)
    float y[4][4];
#pragma unroll
    for (int ni = 0; ni < 4; ni++)
#pragma unroll
        for (int r = 0; r < 4; r++) y[ni][r] = 0.0f;
#pragma unroll
    for (int kk = 0; kk < 64; kk += 16) {
        uint32_t qh[4], ql[4];
        uint32_t ad = sbase + OFF_QH2 + a_lane + (uint32_t)(kk * 2);
        ldmx4(qh, ad);
        ldmx4(ql, ad + (OFF_QL2 - OFF_QH2));
        uint32_t bsh[4][2], bsl[4][2];
#pragma unroll
        for (int np = 0; np < 2; np++) {
            uint32_t bd = sbase + OFF_SPH2 + b_lane + (uint32_t)((np * 16 * TPAD + kk) * 2);
            uint32_t r4[4];
            ldmx4(r4, bd);
            bsh[np * 2][0] = r4[0]; bsh[np * 2][1] = r4[1];
            bsh[np * 2 + 1][0] = r4[2]; bsh[np * 2 + 1][1] = r4[3];
            ldmx4(r4, bd + (OFF_SPL2 - OFF_SPH2));
            bsl[np * 2][0] = r4[0]; bsl[np * 2][1] = r4[1];
            bsl[np * 2 + 1][0] = r4[2]; bsl[np * 2 + 1][1] = r4[3];
        }
#pragma unroll
        for (int ni = 0; ni < 4; ni++) {
            mma_f16(y[ni], qh, bsh[ni]);
            mma_f16(y[ni], qh, bsl[ni]);
            mma_f16(y[ni], ql, bsh[ni]);
        }
    }

    __syncthreads();   // Am published

    // ---- phase 2a: y += Am·V (3-term)
#pragma unroll
    for (int kk = 0; kk < 64; kk += 16) {
        uint32_t amh[4], aml[4];
        uint32_t ad = sbase + OFF_AH2 + a_lane + (uint32_t)(kk * 2);
        ldmx4(amh, ad);
        ldmx4(aml, ad + (OFF_AL2 - OFF_AH2));
        uint32_t bvh[4][2], bvl[4][2];
#pragma unroll
        for (int np = 0; np < 2; np++) {
            uint32_t bd = sbase + OFF_VTH2 + b_lane + (uint32_t)((np * 16 * TPAD + kk) * 2);
            uint32_t r4[4];
            ldmx4(r4, bd);
            bvh[np * 2][0] = r4[0]; bvh[np * 2][1] = r4[1];
            bvh[np * 2 + 1][0] = r4[2]; bvh[np * 2 + 1][1] = r4[3];
            ldmx4(r4, bd + (OFF_VTL2 - OFF_VTH2));
            bvl[np * 2][0] = r4[0]; bvl[np * 2][1] = r4[1];
            bvl[np * 2 + 1][0] = r4[2]; bvl[np * 2 + 1][1] = r4[3];
        }
#pragma unroll
        for (int ni = 0; ni < 4; ni++) {
            mma_f16(y[ni], amh, bvh[ni]);
            mma_f16(y[ni], amh, bvl[ni]);
            mma_f16(y[ni], aml, bvh[ni]);
        }
    }

    // ---- epilogue: write Y as fp16 ROW-MAJOR into g_Y16 (m = b*T + t, k = h*64 + p)
    const int b = bh >> 4, h = bh & 15;
    const int mbase = b * Tt + c * CH;
#pragma unroll
    for (int ni = 0; ni < 4; ni++) {
        int p = nw + ni * 8 + lcol2;
        int k = h * HDim + p;
        int m0 = mbase + mw + lrow, m1 = m0 + 8;
        *(uint32_t*)(g_Y16 + (size_t)m0 * Dd + k) = packh(y[ni][0], y[ni][1]);
        *(uint32_t*)(g_Y16 + (size_t)m1 * Dd + k) = packh(y[ni][2], y[ni][3]);
    }
}

// ---------------------------------------------------------------------------
extern "C" void kernel_launch(void* const* d_in, const int* in_sizes, int n_in,
                              void* d_out, int out_size)
{
    const float* x  = (const float*)d_in[0];
    const float* Wq = (const float*)d_in[1];
    const float* bq = (const float*)d_in[2];
    const float* Wk = (const float*)d_in[3];
    const float* bk = (const float*)d_in[4];
    const float* Wv = (const float*)d_in[5];
    const float* bv = (const float*)d_in[6];
    const float* Wo = (const float*)d_in[7];
    const float* bo = (const float*)d_in[8];
    float* out = (float*)d_out;

    cudaFuncSetAttribute(tc_gemm, cudaFuncAttributeMaxDynamicSharedMemorySize, GEMM_SMEM);
    cudaFuncSetAttribute(chunk_sums_tc, cudaFuncAttributeMaxDynamicSharedMemorySize, CS_SMEM);
    cudaFuncSetAttribute(attn_tc, cudaFuncAttributeMaxDynamicSharedMemorySize, ATTN_SMEM);

    convert_x<<<BT * Dd / 4 / 256, 256>>>((const float4*)x);
    convert_w<<<dim3(Dd * Dd / 4 / 256, 4), 256>>>((const float4*)Wq, (const float4*)Wk,
                                                   (const float4*)Wv, (const float4*)Wo);
    tc_gemm<<<dim3(Dd / TN, BT / TM, 3), 256, GEMM_SMEM>>>(bq, bk, bv, nullptr, 0);
    chunk_sums_tc<<<dim3(NCH, BHn), 256, CS_SMEM>>>();
    prefix_kernel<<<dim3(BHn, 16), 256>>>();
    attn_tc<<<dim3(NCH, BHn), 256, ATTN_SMEM>>>();
    tc_gemm<<<dim3(Dd / TN, BT / TM, 1), 256, GEMM_SMEM>>>(bo, nullptr, nullptr, out, 1);
}